// round 1
// baseline (speedup 1.0000x reference)
#include <cuda_runtime.h>
#include <math.h>

#define Bb 8
#define Tt 256
#define Ss 256
#define Hh 512
#define BT (Bb*Tt)

// Scratch (device globals; no allocation allowed)
__device__ float g_TA[BT * Hh];      // tanh(query @ W_s^T)   (B,T,H)
__device__ float g_TB[Bb * Ss * Hh]; // tanh(enc   @ W_h^T)   (B,S,H)
__device__ float g_CTX[BT * Hh];     // context               (B,T,H)

// ---------------------------------------------------------------------------
// GEMM: C[M,N] = tanh( A @ W^T ), W row-major (N x K).
// A is logically [M,K], split column-wise: cols [0,kSplit) from A1 (row stride
// kSplit), cols [kSplit,K) from A2 (row stride K-kSplit). For a plain GEMM
// pass A2=A1, kSplit=K.
// Tiles: BM=BN=64, BK=16, 256 threads, 4x4 per-thread register tile.
// ---------------------------------------------------------------------------
__global__ __launch_bounds__(256) void gemm_nt_tanh(
    const float* __restrict__ A1, const float* __restrict__ A2, int kSplit,
    const float* __restrict__ W, float* __restrict__ C, int K, int N)
{
    __shared__ float As[16][68];
    __shared__ float Wsm[16][68];

    const int tid = threadIdx.x;
    const int m0 = blockIdx.y * 64;
    const int n0 = blockIdx.x * 64;
    const int ty = tid >> 4;        // 0..15 -> C row group
    const int tx = tid & 15;        // 0..15 -> C col group
    const int lm = tid >> 2;        // 0..63 row within tile for loads
    const int lk = (tid & 3) * 4;   // 0,4,8,12 k offset for loads

    float acc[4][4];
    #pragma unroll
    for (int i = 0; i < 4; i++)
        #pragma unroll
        for (int j = 0; j < 4; j++) acc[i][j] = 0.0f;

    for (int k0 = 0; k0 < K; k0 += 16) {
        // ---- stage A tile (transposed into smem) ----
        {
            int gk = k0 + lk;
            const float* src;
            int stride;
            if (gk < kSplit) { src = A1; stride = kSplit; }
            else             { src = A2; stride = K - kSplit; gk -= kSplit; }
            float4 a = *reinterpret_cast<const float4*>(&src[(size_t)(m0 + lm) * stride + gk]);
            As[lk + 0][lm] = a.x; As[lk + 1][lm] = a.y;
            As[lk + 2][lm] = a.z; As[lk + 3][lm] = a.w;

            float4 w = *reinterpret_cast<const float4*>(&W[(size_t)(n0 + lm) * K + k0 + lk]);
            Wsm[lk + 0][lm] = w.x; Wsm[lk + 1][lm] = w.y;
            Wsm[lk + 2][lm] = w.z; Wsm[lk + 3][lm] = w.w;
        }
        __syncthreads();

        #pragma unroll
        for (int k = 0; k < 16; k++) {
            float4 a4 = *reinterpret_cast<const float4*>(&As[k][ty * 4]);
            float4 w4 = *reinterpret_cast<const float4*>(&Wsm[k][tx * 4]);
            float av[4] = {a4.x, a4.y, a4.z, a4.w};
            float wv[4] = {w4.x, w4.y, w4.z, w4.w};
            #pragma unroll
            for (int i = 0; i < 4; i++)
                #pragma unroll
                for (int j = 0; j < 4; j++)
                    acc[i][j] = fmaf(av[i], wv[j], acc[i][j]);
        }
        __syncthreads();
    }

    #pragma unroll
    for (int i = 0; i < 4; i++) {
        float4 o;
        o.x = tanhf(acc[i][0]);
        o.y = tanhf(acc[i][1]);
        o.z = tanhf(acc[i][2]);
        o.w = tanhf(acc[i][3]);
        *reinterpret_cast<float4*>(&C[(size_t)(m0 + ty * 4 + i) * N + n0 + tx * 4]) = o;
    }
}

// ---------------------------------------------------------------------------
// Fused energies + softmax + context.
// Block: 256 threads handles (b, 16 consecutive t).
// energies(t,s) = sum_h v[h] * (ta+tb)/(1+ta*tb)   [tanh addition identity]
// Then row softmax (with length mask) and context = weights @ enc.
// smem: qa[16][513], eb[32][513], vb[512], en[16][256]  (~114 KB dynamic)
// ---------------------------------------------------------------------------
__global__ __launch_bounds__(256) void attn_ctx_kernel(
    const float* __restrict__ enc, const float* __restrict__ v,
    const int* __restrict__ lens, float* __restrict__ ctx)
{
    extern __shared__ float sm[];
    float* qa = sm;                   // 16*513
    float* eb = qa + 16 * 513;        // 32*513
    float* vb = eb + 32 * 513;        // 512
    float* en = vb + 512;             // 16*256

    const int tid = threadIdx.x;
    const int b = blockIdx.y;
    const int t0 = blockIdx.x * 16;
    const int len = lens[b];

    // load qa (16 x 512 of g_TA) and v into smem
    for (int i = tid * 4; i < 16 * 512; i += 1024) {
        int t = i >> 9, h = i & 511;
        float4 x = *reinterpret_cast<const float4*>(&g_TA[(size_t)(b * Tt + t0 + t) * Hh + h]);
        float* d = &qa[t * 513 + h];
        d[0] = x.x; d[1] = x.y; d[2] = x.z; d[3] = x.w;
    }
    if (tid * 4 < 512) {
        float4 x = *reinterpret_cast<const float4*>(&v[tid * 4]);
        vb[tid * 4 + 0] = x.x; vb[tid * 4 + 1] = x.y;
        vb[tid * 4 + 2] = x.z; vb[tid * 4 + 3] = x.w;
    }

    const int ti = tid >> 4;   // 0..15 : t within tile
    const int si = tid & 15;   // 0..15 : s pair base (handles si and si+16)

    // ---- Phase A: energies over 8 s-tiles of 32 ----
    for (int st = 0; st < 8; st++) {
        int s0 = st * 32;
        for (int i = tid * 4; i < 32 * 512; i += 1024) {
            int s = i >> 9, h = i & 511;
            float4 x = *reinterpret_cast<const float4*>(&g_TB[(size_t)(b * Ss + s0 + s) * Hh + h]);
            float* d = &eb[s * 513 + h];
            d[0] = x.x; d[1] = x.y; d[2] = x.z; d[3] = x.w;
        }
        __syncthreads();

        float acc0 = 0.0f, acc1 = 0.0f;
        const float* qrow = &qa[ti * 513];
        const float* er0 = &eb[si * 513];
        const float* er1 = &eb[(si + 16) * 513];
        #pragma unroll 8
        for (int h = 0; h < 512; h++) {
            float ta = qrow[h];
            float vh = vb[h];
            float tb0 = er0[h];
            float tb1 = er1[h];
            float d0 = fmaf(ta, tb0, 1.0f);
            float d1 = fmaf(ta, tb1, 1.0f);
            float num0 = ta + tb0;
            float num1 = ta + tb1;
            float r0, r1;
            asm("rcp.approx.f32 %0, %1;" : "=f"(r0) : "f"(d0));
            asm("rcp.approx.f32 %0, %1;" : "=f"(r1) : "f"(d1));
            acc0 = fmaf(vh, num0 * r0, acc0);
            acc1 = fmaf(vh, num1 * r1, acc1);
        }
        en[ti * 256 + s0 + si]      = (s0 + si      < len) ? acc0 : -INFINITY;
        en[ti * 256 + s0 + si + 16] = (s0 + si + 16 < len) ? acc1 : -INFINITY;
        __syncthreads();
    }

    // ---- Phase B: row softmax (16 threads per row; shfl within 16-lane groups) ----
    {
        float m = -INFINITY;
        for (int s = si; s < 256; s += 16) m = fmaxf(m, en[ti * 256 + s]);
        #pragma unroll
        for (int o = 8; o; o >>= 1) m = fmaxf(m, __shfl_xor_sync(0xffffffffu, m, o));
        float sum = 0.0f;
        for (int s = si; s < 256; s += 16) {
            float e = __expf(en[ti * 256 + s] - m);
            en[ti * 256 + s] = e;
            sum += e;
        }
        #pragma unroll
        for (int o = 8; o; o >>= 1) sum += __shfl_xor_sync(0xffffffffu, sum, o);
        float rs = 1.0f / sum;
        for (int s = si; s < 256; s += 16) en[ti * 256 + s] *= rs;
    }
    __syncthreads();

    // ---- Phase C: context[t, :] = sum_s w[t,s] * enc[b,s,:] ----
    float acc[32];
    #pragma unroll
    for (int j = 0; j < 32; j++) acc[j] = 0.0f;

    for (int st = 0; st < 16; st++) {
        int s0 = st * 16;
        for (int i = tid * 4; i < 16 * 512; i += 1024) {
            int s = i >> 9, h = i & 511;
            float4 x = *reinterpret_cast<const float4*>(&enc[(size_t)(b * Ss + s0 + s) * Hh + h]);
            float* d = &eb[s * 513 + h];
            d[0] = x.x; d[1] = x.y; d[2] = x.z; d[3] = x.w;
        }
        __syncthreads();
        #pragma unroll 4
        for (int ss = 0; ss < 16; ss++) {
            float w = en[ti * 256 + s0 + ss];
            const float* er = &eb[ss * 513 + si];
            #pragma unroll
            for (int j = 0; j < 32; j++)
                acc[j] = fmaf(w, er[j * 16], acc[j]);
        }
        __syncthreads();
    }

    #pragma unroll
    for (int j = 0; j < 32; j++)
        ctx[(size_t)(b * Tt + t0 + ti) * Hh + si + j * 16] = acc[j];
}

// ---------------------------------------------------------------------------
extern "C" void kernel_launch(void* const* d_in, const int* in_sizes, int n_in,
                              void* d_out, int out_size)
{
    const float* query = (const float*)d_in[0];
    const float* enc   = (const float*)d_in[1];
    const int*   lens  = (const int*)d_in[2];
    const float* W_s   = (const float*)d_in[3];
    const float* W_h   = (const float*)d_in[4];
    const float* v     = (const float*)d_in[5];
    const float* W_out = (const float*)d_in[6];
    float* out = (float*)d_out;

    float *TA, *TB, *CTX;
    cudaGetSymbolAddress((void**)&TA, g_TA);
    cudaGetSymbolAddress((void**)&TB, g_TB);
    cudaGetSymbolAddress((void**)&CTX, g_CTX);

    const int SMEM = (16 * 513 + 32 * 513 + 512 + 16 * 256) * 4; // 116928 B
    cudaFuncSetAttribute(attn_ctx_kernel,
                         cudaFuncAttributeMaxDynamicSharedMemorySize, SMEM);

    // K1: TA = tanh(query @ W_s^T)   (2048 x 512, K=512)
    gemm_nt_tanh<<<dim3(Hh / 64, BT / 64), 256>>>(query, query, 512, W_s, TA, 512, Hh);
    // K2: TB = tanh(enc @ W_h^T)     (2048 x 512, K=512)
    gemm_nt_tanh<<<dim3(Hh / 64, (Bb * Ss) / 64), 256>>>(enc, enc, 512, W_h, TB, 512, Hh);
    // K3: energies + softmax + context
    attn_ctx_kernel<<<dim3(Tt / 16, Bb), 256, SMEM>>>(enc, v, lens, CTX);
    // K4: out = tanh([context|query] @ W_out^T)  (2048 x 512, K=1024)
    gemm_nt_tanh<<<dim3(Hh / 64, BT / 64), 256>>>(CTX, query, 512, W_out, out, 1024, Hh);
}

// round 5
// speedup vs baseline: 1.2543x; 1.2543x over previous
#include <cuda_runtime.h>
#include <cuda_bf16.h>
#include <math.h>
#include <stdint.h>

#define Bb 8
#define Tt 256
#define Ss 256
#define Hh 512
#define BT (Bb*Tt)

// ------------------------- scratch (device globals) -------------------------
__device__ float g_TA[BT * Hh];       // tanh(query @ W_s^T)
__device__ float g_TB[Bb * Ss * Hh];  // tanh(enc   @ W_h^T)
__device__ float g_CTX[BT * Hh];      // context

__device__ __nv_bfloat16 g_qh[BT * Hh],  g_ql[BT * Hh];
__device__ __nv_bfloat16 g_eh[Bb*Ss*Hh], g_el[Bb*Ss*Hh];
__device__ __nv_bfloat16 g_wsh[Hh*Hh],   g_wsl[Hh*Hh];
__device__ __nv_bfloat16 g_whh[Hh*Hh],   g_whl[Hh*Hh];
__device__ __nv_bfloat16 g_woh[Hh*2*Hh], g_wol[Hh*2*Hh];
__device__ __nv_bfloat16 g_ch[BT * Hh],  g_cl[BT * Hh];

// ------------------------- helpers -------------------------
__device__ __forceinline__ uint32_t smem_u32(const void* p) {
    uint32_t a;
    asm("{ .reg .u64 t; cvta.to.shared.u64 t, %1; cvt.u32.u64 %0, t; }" : "=r"(a) : "l"(p));
    return a;
}

#define LDSM4(r, addr) \
    asm volatile("ldmatrix.sync.aligned.m8n8.x4.shared.b16 {%0,%1,%2,%3}, [%4];" \
        : "=r"((r)[0]), "=r"((r)[1]), "=r"((r)[2]), "=r"((r)[3]) : "r"(addr))

#define MMA16816(c, a, b) \
    asm volatile("mma.sync.aligned.m16n8k16.row.col.f32.bf16.bf16.f32 " \
        "{%0,%1,%2,%3}, {%4,%5,%6,%7}, {%8,%9}, {%0,%1,%2,%3};" \
        : "+f"((c)[0]), "+f"((c)[1]), "+f"((c)[2]), "+f"((c)[3]) \
        : "r"((a)[0]), "r"((a)[1]), "r"((a)[2]), "r"((a)[3]), "r"((b)[0]), "r"((b)[1]))

// ------------------------- f32 -> bf16 hi/lo split -------------------------
__global__ __launch_bounds__(256) void cvt_hilo(const float* __restrict__ x,
                                                __nv_bfloat16* __restrict__ hi,
                                                __nv_bfloat16* __restrict__ lo, int n4)
{
    int i = blockIdx.x * blockDim.x + threadIdx.x;
    if (i >= n4) return;
    float4 v = reinterpret_cast<const float4*>(x)[i];
    __nv_bfloat16 h0 = __float2bfloat16(v.x), h1 = __float2bfloat16(v.y);
    __nv_bfloat16 h2 = __float2bfloat16(v.z), h3 = __float2bfloat16(v.w);
    __nv_bfloat16 l0 = __float2bfloat16(v.x - __bfloat162float(h0));
    __nv_bfloat16 l1 = __float2bfloat16(v.y - __bfloat162float(h1));
    __nv_bfloat16 l2 = __float2bfloat16(v.z - __bfloat162float(h2));
    __nv_bfloat16 l3 = __float2bfloat16(v.w - __bfloat162float(h3));
    __nv_bfloat162 hp0 = __halves2bfloat162(h0, h1), hp1 = __halves2bfloat162(h2, h3);
    __nv_bfloat162 lp0 = __halves2bfloat162(l0, l1), lp1 = __halves2bfloat162(l2, l3);
    uint2 ho, loo;
    ho.x  = *reinterpret_cast<uint32_t*>(&hp0); ho.y  = *reinterpret_cast<uint32_t*>(&hp1);
    loo.x = *reinterpret_cast<uint32_t*>(&lp0); loo.y = *reinterpret_cast<uint32_t*>(&lp1);
    reinterpret_cast<uint2*>(hi)[i] = ho;
    reinterpret_cast<uint2*>(lo)[i] = loo;
}

// ---------------------------------------------------------------------------
// HMMA bf16x3 GEMM: C = tanh(A @ W^T), fp32-equivalent accuracy.
// A cols [0,kSplit) from (Ah1,Al1), rest from (Ah2,Al2). W row-major [N][K].
// Block 128x64, BK=32, 8 warps (4x2), warp tile 32x32 via m16n8k16.
// SMEM rows padded to 40 bf16 (80B) -> conflict-free ldmatrix.
// ---------------------------------------------------------------------------
__global__ __launch_bounds__(256) void gemm_mma_tanh(
    const __nv_bfloat16* __restrict__ Ah1, const __nv_bfloat16* __restrict__ Al1,
    const __nv_bfloat16* __restrict__ Ah2, const __nv_bfloat16* __restrict__ Al2,
    int kSplit,
    const __nv_bfloat16* __restrict__ Wh, const __nv_bfloat16* __restrict__ Wl,
    float* __restrict__ C, int K, int Nout)
{
    __shared__ __nv_bfloat16 sAh[128][40], sAl[128][40];
    __shared__ __nv_bfloat16 sBh[64][40],  sBl[64][40];

    const int tid = threadIdx.x;
    const int wid = tid >> 5, lane = tid & 31;
    const int wm = (wid & 3) * 32;      // warp m offset in tile
    const int wn = (wid >> 2) * 32;     // warp n offset in tile
    const int m0 = blockIdx.y * 128, n0 = blockIdx.x * 64;

    float acc[2][4][4];
    #pragma unroll
    for (int mi = 0; mi < 2; mi++)
        #pragma unroll
        for (int ni = 0; ni < 4; ni++)
            #pragma unroll
            for (int r = 0; r < 4; r++) acc[mi][ni][r] = 0.0f;

    const int ar = tid >> 2;            // 0..63 (A row; second pass +64)
    const int ac = (tid & 3) * 8;       // k offset 0/8/16/24
    const int g  = lane >> 3;           // ldmatrix lane group 0..3
    const int rr = lane & 7;

    for (int k0 = 0; k0 < K; k0 += 32) {
        const __nv_bfloat16 *pAh, *pAl; int sA, kk;
        if (k0 < kSplit) { pAh = Ah1; pAl = Al1; sA = kSplit;     kk = k0; }
        else             { pAh = Ah2; pAl = Al2; sA = K - kSplit; kk = k0 - kSplit; }

        #pragma unroll
        for (int r = 0; r < 2; r++) {
            int row = ar + r * 64;
            size_t gidx = (size_t)(m0 + row) * sA + kk + ac;
            *reinterpret_cast<float4*>(&sAh[row][ac]) = *reinterpret_cast<const float4*>(&pAh[gidx]);
            *reinterpret_cast<float4*>(&sAl[row][ac]) = *reinterpret_cast<const float4*>(&pAl[gidx]);
        }
        {
            size_t gidx = (size_t)(n0 + ar) * K + k0 + ac;
            *reinterpret_cast<float4*>(&sBh[ar][ac]) = *reinterpret_cast<const float4*>(&Wh[gidx]);
            *reinterpret_cast<float4*>(&sBl[ar][ac]) = *reinterpret_cast<const float4*>(&Wl[gidx]);
        }
        __syncthreads();

        #pragma unroll
        for (int ks = 0; ks < 32; ks += 16) {
            uint32_t ah[2][4], al[2][4], bh[4][2], bl[4][2];
            const int col = ks + (g >> 1) * 8;

            #pragma unroll
            for (int mi = 0; mi < 2; mi++) {
                int row = wm + mi * 16 + (g & 1) * 8 + rr;
                LDSM4(ah[mi], smem_u32(&sAh[row][col]));
                LDSM4(al[mi], smem_u32(&sAl[row][col]));
            }
            #pragma unroll
            for (int nb = 0; nb < 2; nb++) {
                int row = wn + nb * 16 + (g & 1) * 8 + rr;
                uint32_t t[4];
                LDSM4(t, smem_u32(&sBh[row][col]));
                bh[nb*2+0][0] = t[0]; bh[nb*2+0][1] = t[2];
                bh[nb*2+1][0] = t[1]; bh[nb*2+1][1] = t[3];
                LDSM4(t, smem_u32(&sBl[row][col]));
                bl[nb*2+0][0] = t[0]; bl[nb*2+0][1] = t[2];
                bl[nb*2+1][0] = t[1]; bl[nb*2+1][1] = t[3];
            }
            #pragma unroll
            for (int mi = 0; mi < 2; mi++)
                #pragma unroll
                for (int ni = 0; ni < 4; ni++) {
                    MMA16816(acc[mi][ni], ah[mi], bh[ni]);
                    MMA16816(acc[mi][ni], ah[mi], bl[ni]);
                    MMA16816(acc[mi][ni], al[mi], bh[ni]);
                }
        }
        __syncthreads();
    }

    #pragma unroll
    for (int mi = 0; mi < 2; mi++)
        #pragma unroll
        for (int ni = 0; ni < 4; ni++) {
            int row = m0 + wm + mi * 16 + (lane >> 2);
            int col = n0 + wn + ni * 8 + (lane & 3) * 2;
            float2 v0, v1;
            v0.x = tanhf(acc[mi][ni][0]); v0.y = tanhf(acc[mi][ni][1]);
            v1.x = tanhf(acc[mi][ni][2]); v1.y = tanhf(acc[mi][ni][3]);
            *reinterpret_cast<float2*>(&C[(size_t)row * Nout + col]) = v0;
            *reinterpret_cast<float2*>(&C[(size_t)(row + 8) * Nout + col]) = v1;
        }
}

// ---------------------------------------------------------------------------
// Fused energies + softmax + context (unchanged, validated in R1).
// ---------------------------------------------------------------------------
__global__ __launch_bounds__(256) void attn_ctx_kernel(
    const float* __restrict__ enc, const float* __restrict__ v,
    const int* __restrict__ lens, float* __restrict__ ctx)
{
    extern __shared__ float sm[];
    float* qa = sm;
    float* eb = qa + 16 * 513;
    float* vb = eb + 32 * 513;
    float* en = vb + 512;

    const int tid = threadIdx.x;
    const int b = blockIdx.y;
    const int t0 = blockIdx.x * 16;
    const int len = lens[b];

    for (int i = tid * 4; i < 16 * 512; i += 1024) {
        int t = i >> 9, h = i & 511;
        float4 x = *reinterpret_cast<const float4*>(&g_TA[(size_t)(b * Tt + t0 + t) * Hh + h]);
        float* d = &qa[t * 513 + h];
        d[0] = x.x; d[1] = x.y; d[2] = x.z; d[3] = x.w;
    }
    if (tid * 4 < 512) {
        float4 x = *reinterpret_cast<const float4*>(&v[tid * 4]);
        vb[tid * 4 + 0] = x.x; vb[tid * 4 + 1] = x.y;
        vb[tid * 4 + 2] = x.z; vb[tid * 4 + 3] = x.w;
    }

    const int ti = tid >> 4;
    const int si = tid & 15;

    for (int st = 0; st < 8; st++) {
        int s0 = st * 32;
        for (int i = tid * 4; i < 32 * 512; i += 1024) {
            int s = i >> 9, h = i & 511;
            float4 x = *reinterpret_cast<const float4*>(&g_TB[(size_t)(b * Ss + s0 + s) * Hh + h]);
            float* d = &eb[s * 513 + h];
            d[0] = x.x; d[1] = x.y; d[2] = x.z; d[3] = x.w;
        }
        __syncthreads();

        float acc0 = 0.0f, acc1 = 0.0f;
        const float* qrow = &qa[ti * 513];
        const float* er0 = &eb[si * 513];
        const float* er1 = &eb[(si + 16) * 513];
        #pragma unroll 8
        for (int h = 0; h < 512; h++) {
            float ta = qrow[h];
            float vh = vb[h];
            float tb0 = er0[h];
            float tb1 = er1[h];
            float d0 = fmaf(ta, tb0, 1.0f);
            float d1 = fmaf(ta, tb1, 1.0f);
            float num0 = ta + tb0;
            float num1 = ta + tb1;
            float r0, r1;
            asm("rcp.approx.f32 %0, %1;" : "=f"(r0) : "f"(d0));
            asm("rcp.approx.f32 %0, %1;" : "=f"(r1) : "f"(d1));
            acc0 = fmaf(vh, num0 * r0, acc0);
            acc1 = fmaf(vh, num1 * r1, acc1);
        }
        en[ti * 256 + s0 + si]      = (s0 + si      < len) ? acc0 : -INFINITY;
        en[ti * 256 + s0 + si + 16] = (s0 + si + 16 < len) ? acc1 : -INFINITY;
        __syncthreads();
    }

    {
        float m = -INFINITY;
        for (int s = si; s < 256; s += 16) m = fmaxf(m, en[ti * 256 + s]);
        #pragma unroll
        for (int o = 8; o; o >>= 1) m = fmaxf(m, __shfl_xor_sync(0xffffffffu, m, o));
        float sum = 0.0f;
        for (int s = si; s < 256; s += 16) {
            float e = __expf(en[ti * 256 + s] - m);
            en[ti * 256 + s] = e;
            sum += e;
        }
        #pragma unroll
        for (int o = 8; o; o >>= 1) sum += __shfl_xor_sync(0xffffffffu, sum, o);
        float rs = 1.0f / sum;
        for (int s = si; s < 256; s += 16) en[ti * 256 + s] *= rs;
    }
    __syncthreads();

    float acc[32];
    #pragma unroll
    for (int j = 0; j < 32; j++) acc[j] = 0.0f;

    for (int st = 0; st < 16; st++) {
        int s0 = st * 16;
        for (int i = tid * 4; i < 16 * 512; i += 1024) {
            int s = i >> 9, h = i & 511;
            float4 x = *reinterpret_cast<const float4*>(&enc[(size_t)(b * Ss + s0 + s) * Hh + h]);
            float* d = &eb[s * 513 + h];
            d[0] = x.x; d[1] = x.y; d[2] = x.z; d[3] = x.w;
        }
        __syncthreads();
        #pragma unroll 4
        for (int ss = 0; ss < 16; ss++) {
            float w = en[ti * 256 + s0 + ss];
            const float* er = &eb[ss * 513 + si];
            #pragma unroll
            for (int j = 0; j < 32; j++)
                acc[j] = fmaf(w, er[j * 16], acc[j]);
        }
        __syncthreads();
    }

    #pragma unroll
    for (int j = 0; j < 32; j++)
        ctx[(size_t)(b * Tt + t0 + ti) * Hh + si + j * 16] = acc[j];
}

// ---------------------------------------------------------------------------
extern "C" void kernel_launch(void* const* d_in, const int* in_sizes, int n_in,
                              void* d_out, int out_size)
{
    const float* query = (const float*)d_in[0];
    const float* enc   = (const float*)d_in[1];
    const int*   lens  = (const int*)d_in[2];
    const float* W_s   = (const float*)d_in[3];
    const float* W_h   = (const float*)d_in[4];
    const float* v     = (const float*)d_in[5];
    const float* W_out = (const float*)d_in[6];
    float* out = (float*)d_out;

    float *TA, *TB, *CTX;
    cudaGetSymbolAddress((void**)&TA,  g_TA);
    cudaGetSymbolAddress((void**)&TB,  g_TB);
    cudaGetSymbolAddress((void**)&CTX, g_CTX);
    __nv_bfloat16 *qh,*ql,*eh,*el,*wsh,*wsl,*whh,*whl,*woh,*wol,*ch,*cl;
    cudaGetSymbolAddress((void**)&qh,  g_qh);  cudaGetSymbolAddress((void**)&ql,  g_ql);
    cudaGetSymbolAddress((void**)&eh,  g_eh);  cudaGetSymbolAddress((void**)&el,  g_el);
    cudaGetSymbolAddress((void**)&wsh, g_wsh); cudaGetSymbolAddress((void**)&wsl, g_wsl);
    cudaGetSymbolAddress((void**)&whh, g_whh); cudaGetSymbolAddress((void**)&whl, g_whl);
    cudaGetSymbolAddress((void**)&woh, g_woh); cudaGetSymbolAddress((void**)&wol, g_wol);
    cudaGetSymbolAddress((void**)&ch,  g_ch);  cudaGetSymbolAddress((void**)&cl,  g_cl);

    const int SMEM_ATTN = (16 * 513 + 32 * 513 + 512 + 16 * 256) * 4; // 116928 B
    cudaFuncSetAttribute(attn_ctx_kernel,
                         cudaFuncAttributeMaxDynamicSharedMemorySize, SMEM_ATTN);

    // convert inputs to bf16 hi/lo
    cvt_hilo<<<(BT*Hh/4 + 255)/256, 256>>>(query, qh, ql, BT*Hh/4);
    cvt_hilo<<<(Bb*Ss*Hh/4 + 255)/256, 256>>>(enc, eh, el, Bb*Ss*Hh/4);
    cvt_hilo<<<(Hh*Hh/4 + 255)/256, 256>>>(W_s, wsh, wsl, Hh*Hh/4);
    cvt_hilo<<<(Hh*Hh/4 + 255)/256, 256>>>(W_h, whh, whl, Hh*Hh/4);
    cvt_hilo<<<(Hh*2*Hh/4 + 255)/256, 256>>>(W_out, woh, wol, Hh*2*Hh/4);

    // K1: TA = tanh(query @ W_s^T)   M=2048 N=512 K=512
    gemm_mma_tanh<<<dim3(Hh/64, BT/128), 256>>>(qh, ql, qh, ql, 512, wsh, wsl, TA, 512, Hh);
    // K2: TB = tanh(enc @ W_h^T)
    gemm_mma_tanh<<<dim3(Hh/64, (Bb*Ss)/128), 256>>>(eh, el, eh, el, 512, whh, whl, TB, 512, Hh);
    // K3: energies + softmax + context
    attn_ctx_kernel<<<dim3(Tt/16, Bb), 256, SMEM_ATTN>>>(enc, v, lens, CTX);
    // convert context
    cvt_hilo<<<(BT*Hh/4 + 255)/256, 256>>>(CTX, ch, cl, BT*Hh/4);
    // K4: out = tanh([context|query] @ W_out^T)  K=1024
    gemm_mma_tanh<<<dim3(Hh/64, BT/128), 256>>>(ch, cl, qh, ql, 512, woh, wol, out, 1024, Hh);
}

// round 6
// speedup vs baseline: 1.4183x; 1.1307x over previous
#include <cuda_runtime.h>
#include <cuda_bf16.h>
#include <math.h>
#include <stdint.h>

#define Bb 8
#define Tt 256
#define Ss 256
#define Hh 512
#define BT (Bb*Tt)

// ------------------------- scratch (device globals) -------------------------
__device__ float g_TA[BT * Hh];       // exp(2 * query @ W_s^T)
__device__ float g_TB[Bb * Ss * Hh];  // exp(2 * enc   @ W_h^T)
__device__ float g_CTX[BT * Hh];      // context

__device__ __nv_bfloat16 g_qh[BT * Hh],  g_ql[BT * Hh];
__device__ __nv_bfloat16 g_eh[Bb*Ss*Hh], g_el[Bb*Ss*Hh];
__device__ __nv_bfloat16 g_wsh[Hh*Hh],   g_wsl[Hh*Hh];
__device__ __nv_bfloat16 g_whh[Hh*Hh],   g_whl[Hh*Hh];
__device__ __nv_bfloat16 g_woh[Hh*2*Hh], g_wol[Hh*2*Hh];
__device__ __nv_bfloat16 g_ch[BT * Hh],  g_cl[BT * Hh];

// ------------------------- helpers -------------------------
__device__ __forceinline__ uint32_t smem_u32(const void* p) {
    uint32_t a;
    asm("{ .reg .u64 t; cvta.to.shared.u64 t, %1; cvt.u32.u64 %0, t; }" : "=r"(a) : "l"(p));
    return a;
}

#define LDSM4(r, addr) \
    asm volatile("ldmatrix.sync.aligned.m8n8.x4.shared.b16 {%0,%1,%2,%3}, [%4];" \
        : "=r"((r)[0]), "=r"((r)[1]), "=r"((r)[2]), "=r"((r)[3]) : "r"(addr))

#define MMA16816(c, a, b) \
    asm volatile("mma.sync.aligned.m16n8k16.row.col.f32.bf16.bf16.f32 " \
        "{%0,%1,%2,%3}, {%4,%5,%6,%7}, {%8,%9}, {%0,%1,%2,%3};" \
        : "+f"((c)[0]), "+f"((c)[1]), "+f"((c)[2]), "+f"((c)[3]) \
        : "r"((a)[0]), "r"((a)[1]), "r"((a)[2]), "r"((a)[3]), "r"((b)[0]), "r"((b)[1]))

#define CP16(dst, src) \
    asm volatile("cp.async.cg.shared.global [%0], [%1], 16;" :: "r"(dst), "l"(src))
#define CP_COMMIT() asm volatile("cp.async.commit_group;")

// ------------------------- f32 -> bf16 hi/lo split -------------------------
__device__ __forceinline__ void cvt4(const float* __restrict__ x,
                                     __nv_bfloat16* __restrict__ hi,
                                     __nv_bfloat16* __restrict__ lo, int i)
{
    float4 v = reinterpret_cast<const float4*>(x)[i];
    __nv_bfloat16 h0 = __float2bfloat16(v.x), h1 = __float2bfloat16(v.y);
    __nv_bfloat16 h2 = __float2bfloat16(v.z), h3 = __float2bfloat16(v.w);
    __nv_bfloat16 l0 = __float2bfloat16(v.x - __bfloat162float(h0));
    __nv_bfloat16 l1 = __float2bfloat16(v.y - __bfloat162float(h1));
    __nv_bfloat16 l2 = __float2bfloat16(v.z - __bfloat162float(h2));
    __nv_bfloat16 l3 = __float2bfloat16(v.w - __bfloat162float(h3));
    __nv_bfloat162 hp0 = __halves2bfloat162(h0, h1), hp1 = __halves2bfloat162(h2, h3);
    __nv_bfloat162 lp0 = __halves2bfloat162(l0, l1), lp1 = __halves2bfloat162(l2, l3);
    uint2 ho, loo;
    ho.x  = *reinterpret_cast<uint32_t*>(&hp0); ho.y  = *reinterpret_cast<uint32_t*>(&hp1);
    loo.x = *reinterpret_cast<uint32_t*>(&lp0); loo.y = *reinterpret_cast<uint32_t*>(&lp1);
    reinterpret_cast<uint2*>(hi)[i] = ho;
    reinterpret_cast<uint2*>(lo)[i] = loo;
}

// fused conversion of the 5 input tensors (sizes in float4 units)
#define N4_Q  (BT*Hh/4)        // 262144
#define N4_E  (Bb*Ss*Hh/4)     // 262144
#define N4_WS (Hh*Hh/4)        // 65536
#define N4_WO (Hh*2*Hh/4)      // 131072
__global__ __launch_bounds__(256) void cvt_all(
    const float* q, const float* e, const float* ws, const float* wh, const float* wo,
    __nv_bfloat16* qh, __nv_bfloat16* ql, __nv_bfloat16* eh, __nv_bfloat16* el,
    __nv_bfloat16* wsh, __nv_bfloat16* wsl, __nv_bfloat16* whh, __nv_bfloat16* whl,
    __nv_bfloat16* woh, __nv_bfloat16* wol)
{
    int i = blockIdx.x * blockDim.x + threadIdx.x;
    if (i < N4_Q)  { cvt4(q,  qh,  ql,  i); return; }  i -= N4_Q;
    if (i < N4_E)  { cvt4(e,  eh,  el,  i); return; }  i -= N4_E;
    if (i < N4_WS) { cvt4(ws, wsh, wsl, i); return; }  i -= N4_WS;
    if (i < N4_WS) { cvt4(wh, whh, whl, i); return; }  i -= N4_WS;
    if (i < N4_WO) { cvt4(wo, woh, wol, i); }
}

__global__ __launch_bounds__(256) void cvt_hilo(const float* __restrict__ x,
                                                __nv_bfloat16* __restrict__ hi,
                                                __nv_bfloat16* __restrict__ lo, int n4)
{
    int i = blockIdx.x * blockDim.x + threadIdx.x;
    if (i < n4) cvt4(x, hi, lo, i);
}

// ---------------------------------------------------------------------------
// HMMA bf16x3 GEMM, 2-stage cp.async pipeline.
// C = epi(A @ W^T); epi: mode 0 -> tanhf, mode 1 -> expf(2x).
// A cols [0,kSplit) from (Ah1,Al1), rest from (Ah2,Al2). W row-major [N][K].
// Block 128x64, BK=32, 8 warps (4x2), warp tile 32x32 via m16n8k16.
// SMEM rows padded to 40 bf16 (80B) -> conflict-free ldmatrix.
// ---------------------------------------------------------------------------
#define OFF_AH 0
#define OFF_AL 10240
#define OFF_BH 20480
#define OFF_BL 25600
#define STG    30720
#define GEMM_SMEM (2*STG)

__global__ __launch_bounds__(256) void gemm_mma_epi(
    const __nv_bfloat16* __restrict__ Ah1, const __nv_bfloat16* __restrict__ Al1,
    const __nv_bfloat16* __restrict__ Ah2, const __nv_bfloat16* __restrict__ Al2,
    int kSplit,
    const __nv_bfloat16* __restrict__ Wh, const __nv_bfloat16* __restrict__ Wl,
    float* __restrict__ C, int K, int Nout, int mode)
{
    extern __shared__ char smem[];
    const uint32_t sb = smem_u32(smem);

    const int tid = threadIdx.x;
    const int wid = tid >> 5, lane = tid & 31;
    const int wm = (wid & 3) * 32;
    const int wn = (wid >> 2) * 32;
    const int m0 = blockIdx.y * 128, n0 = blockIdx.x * 64;

    const int ar = tid >> 2;            // 0..63
    const int ac = (tid & 3) * 8;       // 0/8/16/24
    const int g  = lane >> 3;
    const int rr = lane & 7;

    float acc[2][4][4];
    #pragma unroll
    for (int mi = 0; mi < 2; mi++)
        #pragma unroll
        for (int ni = 0; ni < 4; ni++)
            #pragma unroll
            for (int r = 0; r < 4; r++) acc[mi][ni][r] = 0.0f;

    auto load_stage = [&](int kc, int stg) {
        const int k0 = kc * 32;
        const __nv_bfloat16 *pAh, *pAl; int sA, kk;
        if (k0 < kSplit) { pAh = Ah1; pAl = Al1; sA = kSplit;     kk = k0; }
        else             { pAh = Ah2; pAl = Al2; sA = K - kSplit; kk = k0 - kSplit; }
        const uint32_t base = sb + stg * STG;
        #pragma unroll
        for (int r = 0; r < 2; r++) {
            int row = ar + r * 64;
            size_t gidx = (size_t)(m0 + row) * sA + kk + ac;
            CP16(base + OFF_AH + row * 80 + ac * 2, &pAh[gidx]);
            CP16(base + OFF_AL + row * 80 + ac * 2, &pAl[gidx]);
        }
        size_t gw = (size_t)(n0 + ar) * K + k0 + ac;
        CP16(base + OFF_BH + ar * 80 + ac * 2, &Wh[gw]);
        CP16(base + OFF_BL + ar * 80 + ac * 2, &Wl[gw]);
    };

    auto compute = [&](int stg) {
        const uint32_t base = sb + stg * STG;
        #pragma unroll
        for (int ks = 0; ks < 32; ks += 16) {
            uint32_t ah[2][4], al[2][4], bh[4][2], bl[4][2];
            const int colb = (ks + (g >> 1) * 8) * 2;
            #pragma unroll
            for (int mi = 0; mi < 2; mi++) {
                int row = wm + mi * 16 + (g & 1) * 8 + rr;
                LDSM4(ah[mi], base + OFF_AH + row * 80 + colb);
                LDSM4(al[mi], base + OFF_AL + row * 80 + colb);
            }
            #pragma unroll
            for (int nb = 0; nb < 2; nb++) {
                int row = wn + nb * 16 + (g & 1) * 8 + rr;
                uint32_t t[4];
                LDSM4(t, base + OFF_BH + row * 80 + colb);
                bh[nb*2+0][0] = t[0]; bh[nb*2+0][1] = t[2];
                bh[nb*2+1][0] = t[1]; bh[nb*2+1][1] = t[3];
                LDSM4(t, base + OFF_BL + row * 80 + colb);
                bl[nb*2+0][0] = t[0]; bl[nb*2+0][1] = t[2];
                bl[nb*2+1][0] = t[1]; bl[nb*2+1][1] = t[3];
            }
            #pragma unroll
            for (int mi = 0; mi < 2; mi++)
                #pragma unroll
                for (int ni = 0; ni < 4; ni++) {
                    MMA16816(acc[mi][ni], ah[mi], bh[ni]);
                    MMA16816(acc[mi][ni], ah[mi], bl[ni]);
                    MMA16816(acc[mi][ni], al[mi], bh[ni]);
                }
        }
    };

    const int NC = K / 32;
    load_stage(0, 0);
    CP_COMMIT();
    for (int kc = 0; kc < NC; kc++) {
        if (kc + 1 < NC) {
            load_stage(kc + 1, (kc + 1) & 1);
            CP_COMMIT();
            asm volatile("cp.async.wait_group 1;");
        } else {
            asm volatile("cp.async.wait_group 0;");
        }
        __syncthreads();
        compute(kc & 1);
        __syncthreads();
    }

    #pragma unroll
    for (int mi = 0; mi < 2; mi++)
        #pragma unroll
        for (int ni = 0; ni < 4; ni++) {
            int row = m0 + wm + mi * 16 + (lane >> 2);
            int col = n0 + wn + ni * 8 + (lane & 3) * 2;
            float2 v0, v1;
            if (mode) {
                v0.x = __expf(2.0f * acc[mi][ni][0]); v0.y = __expf(2.0f * acc[mi][ni][1]);
                v1.x = __expf(2.0f * acc[mi][ni][2]); v1.y = __expf(2.0f * acc[mi][ni][3]);
            } else {
                v0.x = tanhf(acc[mi][ni][0]); v0.y = tanhf(acc[mi][ni][1]);
                v1.x = tanhf(acc[mi][ni][2]); v1.y = tanhf(acc[mi][ni][3]);
            }
            *reinterpret_cast<float2*>(&C[(size_t)row * Nout + col]) = v0;
            *reinterpret_cast<float2*>(&C[(size_t)(row + 8) * Nout + col]) = v1;
        }
}

// ---------------------------------------------------------------------------
// Fused energies + softmax + context.
// energies use exp-form: tanh(a+b) = 1 - 2/(Ea*Eb+1); the constant
// sum_h v_h cancels in softmax, so en = -2 * sum_h v_h / (Ea*Eb + 1).
// ---------------------------------------------------------------------------
__global__ __launch_bounds__(256) void attn_ctx_kernel(
    const float* __restrict__ enc, const float* __restrict__ v,
    const int* __restrict__ lens, float* __restrict__ ctx)
{
    extern __shared__ float sm[];
    float* qa = sm;
    float* eb = qa + 16 * 513;
    float* vb = eb + 32 * 513;
    float* en = vb + 512;

    const int tid = threadIdx.x;
    const int b = blockIdx.y;
    const int t0 = blockIdx.x * 16;
    const int len = lens[b];

    for (int i = tid * 4; i < 16 * 512; i += 1024) {
        int t = i >> 9, h = i & 511;
        float4 x = *reinterpret_cast<const float4*>(&g_TA[(size_t)(b * Tt + t0 + t) * Hh + h]);
        float* d = &qa[t * 513 + h];
        d[0] = x.x; d[1] = x.y; d[2] = x.z; d[3] = x.w;
    }
    if (tid * 4 < 512) {
        float4 x = *reinterpret_cast<const float4*>(&v[tid * 4]);
        vb[tid * 4 + 0] = x.x; vb[tid * 4 + 1] = x.y;
        vb[tid * 4 + 2] = x.z; vb[tid * 4 + 3] = x.w;
    }

    const int ti = tid >> 4;
    const int si = tid & 15;

    for (int st = 0; st < 8; st++) {
        int s0 = st * 32;
        for (int i = tid * 4; i < 32 * 512; i += 1024) {
            int s = i >> 9, h = i & 511;
            float4 x = *reinterpret_cast<const float4*>(&g_TB[(size_t)(b * Ss + s0 + s) * Hh + h]);
            float* d = &eb[s * 513 + h];
            d[0] = x.x; d[1] = x.y; d[2] = x.z; d[3] = x.w;
        }
        __syncthreads();

        float acc0 = 0.0f, acc1 = 0.0f;
        const float* qrow = &qa[ti * 513];
        const float* er0 = &eb[si * 513];
        const float* er1 = &eb[(si + 16) * 513];
        #pragma unroll 8
        for (int h = 0; h < 512; h++) {
            float Ea = qrow[h];
            float vh = vb[h];
            float d0 = fmaf(Ea, er0[h], 1.0f);
            float d1 = fmaf(Ea, er1[h], 1.0f);
            float r0, r1;
            asm("rcp.approx.f32 %0, %1;" : "=f"(r0) : "f"(d0));
            asm("rcp.approx.f32 %0, %1;" : "=f"(r1) : "f"(d1));
            acc0 = fmaf(vh, r0, acc0);
            acc1 = fmaf(vh, r1, acc1);
        }
        en[ti * 256 + s0 + si]      = (s0 + si      < len) ? (-2.0f * acc0) : -INFINITY;
        en[ti * 256 + s0 + si + 16] = (s0 + si + 16 < len) ? (-2.0f * acc1) : -INFINITY;
        __syncthreads();
    }

    {
        float m = -INFINITY;
        for (int s = si; s < 256; s += 16) m = fmaxf(m, en[ti * 256 + s]);
        #pragma unroll
        for (int o = 8; o; o >>= 1) m = fmaxf(m, __shfl_xor_sync(0xffffffffu, m, o));
        float sum = 0.0f;
        for (int s = si; s < 256; s += 16) {
            float e = __expf(en[ti * 256 + s] - m);
            en[ti * 256 + s] = e;
            sum += e;
        }
        #pragma unroll
        for (int o = 8; o; o >>= 1) sum += __shfl_xor_sync(0xffffffffu, sum, o);
        float rs = 1.0f / sum;
        for (int s = si; s < 256; s += 16) en[ti * 256 + s] *= rs;
    }
    __syncthreads();

    float acc[32];
    #pragma unroll
    for (int j = 0; j < 32; j++) acc[j] = 0.0f;

    for (int st = 0; st < 16; st++) {
        int s0 = st * 16;
        for (int i = tid * 4; i < 16 * 512; i += 1024) {
            int s = i >> 9, h = i & 511;
            float4 x = *reinterpret_cast<const float4*>(&enc[(size_t)(b * Ss + s0 + s) * Hh + h]);
            float* d = &eb[s * 513 + h];
            d[0] = x.x; d[1] = x.y; d[2] = x.z; d[3] = x.w;
        }
        __syncthreads();
        #pragma unroll 4
        for (int ss = 0; ss < 16; ss++) {
            float w = en[ti * 256 + s0 + ss];
            const float* er = &eb[ss * 513 + si];
            #pragma unroll
            for (int j = 0; j < 32; j++)
                acc[j] = fmaf(w, er[j * 16], acc[j]);
        }
        __syncthreads();
    }

    #pragma unroll
    for (int j = 0; j < 32; j++)
        ctx[(size_t)(b * Tt + t0 + ti) * Hh + si + j * 16] = acc[j];
}

// ---------------------------------------------------------------------------
extern "C" void kernel_launch(void* const* d_in, const int* in_sizes, int n_in,
                              void* d_out, int out_size)
{
    const float* query = (const float*)d_in[0];
    const float* enc   = (const float*)d_in[1];
    const int*   lens  = (const int*)d_in[2];
    const float* W_s   = (const float*)d_in[3];
    const float* W_h   = (const float*)d_in[4];
    const float* v     = (const float*)d_in[5];
    const float* W_out = (const float*)d_in[6];
    float* out = (float*)d_out;

    float *TA, *TB, *CTX;
    cudaGetSymbolAddress((void**)&TA,  g_TA);
    cudaGetSymbolAddress((void**)&TB,  g_TB);
    cudaGetSymbolAddress((void**)&CTX, g_CTX);
    __nv_bfloat16 *qh,*ql,*eh,*el,*wsh,*wsl,*whh,*whl,*woh,*wol,*ch,*cl;
    cudaGetSymbolAddress((void**)&qh,  g_qh);  cudaGetSymbolAddress((void**)&ql,  g_ql);
    cudaGetSymbolAddress((void**)&eh,  g_eh);  cudaGetSymbolAddress((void**)&el,  g_el);
    cudaGetSymbolAddress((void**)&wsh, g_wsh); cudaGetSymbolAddress((void**)&wsl, g_wsl);
    cudaGetSymbolAddress((void**)&whh, g_whh); cudaGetSymbolAddress((void**)&whl, g_whl);
    cudaGetSymbolAddress((void**)&woh, g_woh); cudaGetSymbolAddress((void**)&wol, g_wol);
    cudaGetSymbolAddress((void**)&ch,  g_ch);  cudaGetSymbolAddress((void**)&cl,  g_cl);

    const int SMEM_ATTN = (16 * 513 + 32 * 513 + 512 + 16 * 256) * 4; // 116928 B
    cudaFuncSetAttribute(attn_ctx_kernel,
                         cudaFuncAttributeMaxDynamicSharedMemorySize, SMEM_ATTN);
    cudaFuncSetAttribute(gemm_mma_epi,
                         cudaFuncAttributeMaxDynamicSharedMemorySize, GEMM_SMEM);

    // fused conversion of the 5 input tensors
    const int TOT4 = N4_Q + N4_E + 2 * N4_WS + N4_WO;  // 786432
    cvt_all<<<TOT4 / 256, 256>>>(query, enc, W_s, W_h, W_out,
                                 qh, ql, eh, el, wsh, wsl, whh, whl, woh, wol);

    // K1: TA = exp(2 * query @ W_s^T)
    gemm_mma_epi<<<dim3(Hh/64, BT/128), 256, GEMM_SMEM>>>(
        qh, ql, qh, ql, 512, wsh, wsl, TA, 512, Hh, 1);
    // K2: TB = exp(2 * enc @ W_h^T)
    gemm_mma_epi<<<dim3(Hh/64, (Bb*Ss)/128), 256, GEMM_SMEM>>>(
        eh, el, eh, el, 512, whh, whl, TB, 512, Hh, 1);
    // K3: energies + softmax + context
    attn_ctx_kernel<<<dim3(Tt/16, Bb), 256, SMEM_ATTN>>>(enc, v, lens, CTX);
    // convert context
    cvt_hilo<<<(BT*Hh/4 + 255)/256, 256>>>(CTX, ch, cl, BT*Hh/4);
    // K4: out = tanh([context|query] @ W_out^T), K=1024
    gemm_mma_epi<<<dim3(Hh/64, BT/128), 256, GEMM_SMEM>>>(
        ch, cl, qh, ql, 512, woh, wol, out, 1024, Hh, 0);
}

// round 8
// speedup vs baseline: 1.7843x; 1.2580x over previous
#include <cuda_runtime.h>
#include <cuda_bf16.h>
#include <math.h>
#include <stdint.h>

#define Bb 8
#define Tt 256
#define Ss 256
#define Hh 512
#define BT (Bb*Tt)

// ------------------------- scratch (device globals) -------------------------
__device__ float g_TA[BT * Hh];       // exp(2 * query @ W_s^T)
__device__ float g_TB[Bb * Ss * Hh];  // exp(2 * enc   @ W_h^T)

__device__ __nv_bfloat16 g_qh[BT * Hh],  g_ql[BT * Hh];
__device__ __nv_bfloat16 g_eh[Bb*Ss*Hh], g_el[Bb*Ss*Hh];
__device__ __nv_bfloat16 g_wsh[Hh*Hh],   g_wsl[Hh*Hh];
__device__ __nv_bfloat16 g_whh[Hh*Hh],   g_whl[Hh*Hh];
__device__ __nv_bfloat16 g_woh[Hh*2*Hh], g_wol[Hh*2*Hh];
__device__ __nv_bfloat16 g_ch[BT * Hh],  g_cl[BT * Hh];

// ------------------------- helpers -------------------------
__device__ __forceinline__ uint32_t smem_u32(const void* p) {
    uint32_t a;
    asm("{ .reg .u64 t; cvta.to.shared.u64 t, %1; cvt.u32.u64 %0, t; }" : "=r"(a) : "l"(p));
    return a;
}

#define LDSM4(r, addr) \
    asm volatile("ldmatrix.sync.aligned.m8n8.x4.shared.b16 {%0,%1,%2,%3}, [%4];" \
        : "=r"((r)[0]), "=r"((r)[1]), "=r"((r)[2]), "=r"((r)[3]) : "r"(addr))

#define MMA16816(c, a, b) \
    asm volatile("mma.sync.aligned.m16n8k16.row.col.f32.bf16.bf16.f32 " \
        "{%0,%1,%2,%3}, {%4,%5,%6,%7}, {%8,%9}, {%0,%1,%2,%3};" \
        : "+f"((c)[0]), "+f"((c)[1]), "+f"((c)[2]), "+f"((c)[3]) \
        : "r"((a)[0]), "r"((a)[1]), "r"((a)[2]), "r"((a)[3]), "r"((b)[0]), "r"((b)[1]))

#define CP16(dst, src) \
    asm volatile("cp.async.cg.shared.global [%0], [%1], 16;" :: "r"(dst), "l"(src))
#define CP_COMMIT() asm volatile("cp.async.commit_group;")

#define RCPF(r, x) asm("rcp.approx.f32 %0, %1;" : "=f"(r) : "f"(x))

// ------------------------- f32 -> bf16 hi/lo split -------------------------
__device__ __forceinline__ void cvt4(const float* __restrict__ x,
                                     __nv_bfloat16* __restrict__ hi,
                                     __nv_bfloat16* __restrict__ lo, int i)
{
    float4 v = reinterpret_cast<const float4*>(x)[i];
    __nv_bfloat16 h0 = __float2bfloat16(v.x), h1 = __float2bfloat16(v.y);
    __nv_bfloat16 h2 = __float2bfloat16(v.z), h3 = __float2bfloat16(v.w);
    __nv_bfloat16 l0 = __float2bfloat16(v.x - __bfloat162float(h0));
    __nv_bfloat16 l1 = __float2bfloat16(v.y - __bfloat162float(h1));
    __nv_bfloat16 l2 = __float2bfloat16(v.z - __bfloat162float(h2));
    __nv_bfloat16 l3 = __float2bfloat16(v.w - __bfloat162float(h3));
    __nv_bfloat162 hp0 = __halves2bfloat162(h0, h1), hp1 = __halves2bfloat162(h2, h3);
    __nv_bfloat162 lp0 = __halves2bfloat162(l0, l1), lp1 = __halves2bfloat162(l2, l3);
    uint2 ho, loo;
    ho.x  = *reinterpret_cast<uint32_t*>(&hp0); ho.y  = *reinterpret_cast<uint32_t*>(&hp1);
    loo.x = *reinterpret_cast<uint32_t*>(&lp0); loo.y = *reinterpret_cast<uint32_t*>(&lp1);
    reinterpret_cast<uint2*>(hi)[i] = ho;
    reinterpret_cast<uint2*>(lo)[i] = loo;
}

#define N4_Q  (BT*Hh/4)
#define N4_E  (Bb*Ss*Hh/4)
#define N4_WS (Hh*Hh/4)
#define N4_WO (Hh*2*Hh/4)
__global__ __launch_bounds__(256) void cvt_all(
    const float* q, const float* e, const float* ws, const float* wh, const float* wo,
    __nv_bfloat16* qh, __nv_bfloat16* ql, __nv_bfloat16* eh, __nv_bfloat16* el,
    __nv_bfloat16* wsh, __nv_bfloat16* wsl, __nv_bfloat16* whh, __nv_bfloat16* whl,
    __nv_bfloat16* woh, __nv_bfloat16* wol)
{
    int i = blockIdx.x * blockDim.x + threadIdx.x;
    if (i < N4_Q)  { cvt4(q,  qh,  ql,  i); return; }  i -= N4_Q;
    if (i < N4_E)  { cvt4(e,  eh,  el,  i); return; }  i -= N4_E;
    if (i < N4_WS) { cvt4(ws, wsh, wsl, i); return; }  i -= N4_WS;
    if (i < N4_WS) { cvt4(wh, whh, whl, i); return; }  i -= N4_WS;
    if (i < N4_WO) { cvt4(wo, woh, wol, i); }
}

// ---------------------------------------------------------------------------
// HMMA bf16x3 GEMM, 2-stage cp.async pipeline (unchanged from R6 pass).
// ---------------------------------------------------------------------------
#define OFF_AH 0
#define OFF_AL 10240
#define OFF_BH 20480
#define OFF_BL 25600
#define STG    30720
#define GEMM_SMEM (2*STG)

__global__ __launch_bounds__(256) void gemm_mma_epi(
    const __nv_bfloat16* __restrict__ Ah1, const __nv_bfloat16* __restrict__ Al1,
    const __nv_bfloat16* __restrict__ Ah2, const __nv_bfloat16* __restrict__ Al2,
    int kSplit,
    const __nv_bfloat16* __restrict__ Wh, const __nv_bfloat16* __restrict__ Wl,
    float* __restrict__ C, int K, int Nout, int mode)
{
    extern __shared__ char smem[];
    const uint32_t sb = smem_u32(smem);

    const int tid = threadIdx.x;
    const int wid = tid >> 5, lane = tid & 31;
    const int wm = (wid & 3) * 32;
    const int wn = (wid >> 2) * 32;
    const int m0 = blockIdx.y * 128, n0 = blockIdx.x * 64;

    const int ar = tid >> 2;
    const int ac = (tid & 3) * 8;
    const int g  = lane >> 3;
    const int rr = lane & 7;

    float acc[2][4][4];
    #pragma unroll
    for (int mi = 0; mi < 2; mi++)
        #pragma unroll
        for (int ni = 0; ni < 4; ni++)
            #pragma unroll
            for (int r = 0; r < 4; r++) acc[mi][ni][r] = 0.0f;

    auto load_stage = [&](int kc, int stg) {
        const int k0 = kc * 32;
        const __nv_bfloat16 *pAh, *pAl; int sA, kk;
        if (k0 < kSplit) { pAh = Ah1; pAl = Al1; sA = kSplit;     kk = k0; }
        else             { pAh = Ah2; pAl = Al2; sA = K - kSplit; kk = k0 - kSplit; }
        const uint32_t base = sb + stg * STG;
        #pragma unroll
        for (int r = 0; r < 2; r++) {
            int row = ar + r * 64;
            size_t gidx = (size_t)(m0 + row) * sA + kk + ac;
            CP16(base + OFF_AH + row * 80 + ac * 2, &pAh[gidx]);
            CP16(base + OFF_AL + row * 80 + ac * 2, &pAl[gidx]);
        }
        size_t gw = (size_t)(n0 + ar) * K + k0 + ac;
        CP16(base + OFF_BH + ar * 80 + ac * 2, &Wh[gw]);
        CP16(base + OFF_BL + ar * 80 + ac * 2, &Wl[gw]);
    };

    auto compute = [&](int stg) {
        const uint32_t base = sb + stg * STG;
        #pragma unroll
        for (int ks = 0; ks < 32; ks += 16) {
            uint32_t ah[2][4], al[2][4], bh[4][2], bl[4][2];
            const int colb = (ks + (g >> 1) * 8) * 2;
            #pragma unroll
            for (int mi = 0; mi < 2; mi++) {
                int row = wm + mi * 16 + (g & 1) * 8 + rr;
                LDSM4(ah[mi], base + OFF_AH + row * 80 + colb);
                LDSM4(al[mi], base + OFF_AL + row * 80 + colb);
            }
            #pragma unroll
            for (int nb = 0; nb < 2; nb++) {
                int row = wn + nb * 16 + (g & 1) * 8 + rr;
                uint32_t t[4];
                LDSM4(t, base + OFF_BH + row * 80 + colb);
                bh[nb*2+0][0] = t[0]; bh[nb*2+0][1] = t[2];
                bh[nb*2+1][0] = t[1]; bh[nb*2+1][1] = t[3];
                LDSM4(t, base + OFF_BL + row * 80 + colb);
                bl[nb*2+0][0] = t[0]; bl[nb*2+0][1] = t[2];
                bl[nb*2+1][0] = t[1]; bl[nb*2+1][1] = t[3];
            }
            #pragma unroll
            for (int mi = 0; mi < 2; mi++)
                #pragma unroll
                for (int ni = 0; ni < 4; ni++) {
                    MMA16816(acc[mi][ni], ah[mi], bh[ni]);
                    MMA16816(acc[mi][ni], ah[mi], bl[ni]);
                    MMA16816(acc[mi][ni], al[mi], bh[ni]);
                }
        }
    };

    const int NC = K / 32;
    load_stage(0, 0);
    CP_COMMIT();
    for (int kc = 0; kc < NC; kc++) {
        if (kc + 1 < NC) {
            load_stage(kc + 1, (kc + 1) & 1);
            CP_COMMIT();
            asm volatile("cp.async.wait_group 1;");
        } else {
            asm volatile("cp.async.wait_group 0;");
        }
        __syncthreads();
        compute(kc & 1);
        __syncthreads();
    }

    #pragma unroll
    for (int mi = 0; mi < 2; mi++)
        #pragma unroll
        for (int ni = 0; ni < 4; ni++) {
            int row = m0 + wm + mi * 16 + (lane >> 2);
            int col = n0 + wn + ni * 8 + (lane & 3) * 2;
            float2 v0, v1;
            if (mode) {
                v0.x = __expf(2.0f * acc[mi][ni][0]); v0.y = __expf(2.0f * acc[mi][ni][1]);
                v1.x = __expf(2.0f * acc[mi][ni][2]); v1.y = __expf(2.0f * acc[mi][ni][3]);
            } else {
                v0.x = tanhf(acc[mi][ni][0]); v0.y = tanhf(acc[mi][ni][1]);
                v1.x = tanhf(acc[mi][ni][2]); v1.y = tanhf(acc[mi][ni][3]);
            }
            *reinterpret_cast<float2*>(&C[(size_t)row * Nout + col]) = v0;
            *reinterpret_cast<float2*>(&C[(size_t)(row + 8) * Nout + col]) = v1;
        }
}

// ---------------------------------------------------------------------------
// K3: energies + softmax + context, warp-per-t, pair-combined reciprocals.
// 512 threads (warp w <-> row t0+w). Rows padded to 516 floats (bank-quad
// stride 4 -> conflict-free LDS.128). Emits context directly as bf16 hi/lo.
// en(t,s) = -2 * sum_h v_h / (Ea_h*Eb_h + 1)   (+const, cancels in softmax)
// ---------------------------------------------------------------------------
#define PAD 516
#define SMEM_ATTN ((16*PAD + 512 + 32*PAD + 16*256) * 4)

__global__ __launch_bounds__(512) void attn_ctx_kernel(
    const float* __restrict__ enc, const float* __restrict__ v,
    const int* __restrict__ lens)
{
    extern __shared__ float sm[];
    float* qa = sm;                 // 16 x PAD  (Ea rows)
    float* vb = qa + 16 * PAD;      // 512
    float* eb = vb + 512;           // 32 x PAD  (Eb rows / enc rows)
    float* en = eb + 32 * PAD;      // 16 x 256

    const int tid  = threadIdx.x;
    const int w    = tid >> 5;      // warp index = t within tile
    const int lane = tid & 31;
    const int b  = blockIdx.y;
    const int t0 = blockIdx.x * 16;
    const int len = lens[b];

    // load qa (16x512 of g_TA) and v
    #pragma unroll
    for (int it = 0; it < 4; it++) {
        int idx = tid + it * 512;             // 2048 float4
        int row = idx >> 7, c4 = idx & 127;
        float4 x = *reinterpret_cast<const float4*>(
            &g_TA[(size_t)(b * Tt + t0 + row) * Hh + c4 * 4]);
        *reinterpret_cast<float4*>(&qa[row * PAD + c4 * 4]) = x;
    }
    if (tid < 128) {
        *reinterpret_cast<float4*>(&vb[tid * 4]) =
            *reinterpret_cast<const float4*>(&v[tid * 4]);
    }

    // ---- Phase A: energies, s-tiles of 32 (lane owns one s per tile) ----
    const float* qrow = &qa[w * PAD];
    const float* erow = &eb[lane * PAD];
    for (int st = 0; st < 8; st++) {
        const int s0 = st * 32;
        __syncthreads();
        #pragma unroll
        for (int it = 0; it < 8; it++) {
            int idx = tid + it * 512;         // 4096 float4
            int row = idx >> 7, c4 = idx & 127;
            float4 x = *reinterpret_cast<const float4*>(
                &g_TB[(size_t)(b * Ss + s0 + row) * Hh + c4 * 4]);
            *reinterpret_cast<float4*>(&eb[row * PAD + c4 * 4]) = x;
        }
        __syncthreads();

        float acc = 0.0f;
        #pragma unroll 4
        for (int h4 = 0; h4 < 128; h4++) {
            float4 A = *reinterpret_cast<const float4*>(&qrow[h4 * 4]);
            float4 V = *reinterpret_cast<const float4*>(&vb[h4 * 4]);
            float4 E = *reinterpret_cast<const float4*>(&erow[h4 * 4]);
            float d0 = fmaf(A.x, E.x, 1.0f);
            float d1 = fmaf(A.y, E.y, 1.0f);
            float d2 = fmaf(A.z, E.z, 1.0f);
            float d3 = fmaf(A.w, E.w, 1.0f);
            float n01 = fmaf(V.y, d0, V.x * d1);
            float n23 = fmaf(V.w, d2, V.z * d3);
            float p01 = d0 * d1, p23 = d2 * d3;
            float r01, r23;
            RCPF(r01, p01); RCPF(r23, p23);
            acc = fmaf(n01, r01, acc);
            acc = fmaf(n23, r23, acc);
        }
        en[w * 256 + s0 + lane] = (s0 + lane < len) ? (-2.0f * acc) : -INFINITY;
    }
    __syncthreads();

    // ---- Phase B: full-warp softmax over 256 s (8 per lane) ----
    {
        float e[8];
        float m = -INFINITY;
        #pragma unroll
        for (int j = 0; j < 8; j++) {
            e[j] = en[w * 256 + lane + 32 * j];
            m = fmaxf(m, e[j]);
        }
        #pragma unroll
        for (int o = 16; o; o >>= 1) m = fmaxf(m, __shfl_xor_sync(0xffffffffu, m, o));
        float sum = 0.0f;
        #pragma unroll
        for (int j = 0; j < 8; j++) { e[j] = __expf(e[j] - m); sum += e[j]; }
        #pragma unroll
        for (int o = 16; o; o >>= 1) sum += __shfl_xor_sync(0xffffffffu, sum, o);
        float rs; RCPF(rs, sum);
        #pragma unroll
        for (int j = 0; j < 8; j++) en[w * 256 + lane + 32 * j] = e[j] * rs;
    }

    // ---- Phase C: context (lane owns 16 h = 4 float4 chunks) + bf16 emit ----
    float4 a0 = {0,0,0,0}, a1 = {0,0,0,0}, a2 = {0,0,0,0}, a3 = {0,0,0,0};
    for (int st = 0; st < 8; st++) {
        const int s0 = st * 32;
        __syncthreads();
        #pragma unroll
        for (int it = 0; it < 8; it++) {
            int idx = tid + it * 512;
            int row = idx >> 7, c4 = idx & 127;
            float4 x = *reinterpret_cast<const float4*>(
                &enc[(size_t)(b * Ss + s0 + row) * Hh + c4 * 4]);
            *reinterpret_cast<float4*>(&eb[row * PAD + c4 * 4]) = x;
        }
        __syncthreads();
        #pragma unroll 4
        for (int s = 0; s < 32; s++) {
            float wg = en[w * 256 + s0 + s];
            const float* er = &eb[s * PAD];
            float4 E0 = *reinterpret_cast<const float4*>(&er[(lane +  0) * 4]);
            float4 E1 = *reinterpret_cast<const float4*>(&er[(lane + 32) * 4]);
            float4 E2 = *reinterpret_cast<const float4*>(&er[(lane + 64) * 4]);
            float4 E3 = *reinterpret_cast<const float4*>(&er[(lane + 96) * 4]);
            a0.x = fmaf(wg, E0.x, a0.x); a0.y = fmaf(wg, E0.y, a0.y);
            a0.z = fmaf(wg, E0.z, a0.z); a0.w = fmaf(wg, E0.w, a0.w);
            a1.x = fmaf(wg, E1.x, a1.x); a1.y = fmaf(wg, E1.y, a1.y);
            a1.z = fmaf(wg, E1.z, a1.z); a1.w = fmaf(wg, E1.w, a1.w);
            a2.x = fmaf(wg, E2.x, a2.x); a2.y = fmaf(wg, E2.y, a2.y);
            a2.z = fmaf(wg, E2.z, a2.z); a2.w = fmaf(wg, E2.w, a2.w);
            a3.x = fmaf(wg, E3.x, a3.x); a3.y = fmaf(wg, E3.y, a3.y);
            a3.z = fmaf(wg, E3.z, a3.z); a3.w = fmaf(wg, E3.w, a3.w);
        }
    }

    // epilogue: bf16 hi/lo split of context, coalesced 8B stores
    {
        const size_t base = (size_t)(b * Tt + t0 + w) * Hh;
        float4 av[4] = {a0, a1, a2, a3};
        #pragma unroll
        for (int c = 0; c < 4; c++) {
            int h = (lane + 32 * c) * 4;
            float4 x = av[c];
            __nv_bfloat16 h0 = __float2bfloat16(x.x), h1 = __float2bfloat16(x.y);
            __nv_bfloat16 h2 = __float2bfloat16(x.z), h3 = __float2bfloat16(x.w);
            __nv_bfloat16 l0 = __float2bfloat16(x.x - __bfloat162float(h0));
            __nv_bfloat16 l1 = __float2bfloat16(x.y - __bfloat162float(h1));
            __nv_bfloat16 l2 = __float2bfloat16(x.z - __bfloat162float(h2));
            __nv_bfloat16 l3 = __float2bfloat16(x.w - __bfloat162float(h3));
            __nv_bfloat162 hp0 = __halves2bfloat162(h0, h1), hp1 = __halves2bfloat162(h2, h3);
            __nv_bfloat162 lp0 = __halves2bfloat162(l0, l1), lp1 = __halves2bfloat162(l2, l3);
            uint2 ho, lo;
            ho.x = *reinterpret_cast<uint32_t*>(&hp0); ho.y = *reinterpret_cast<uint32_t*>(&hp1);
            lo.x = *reinterpret_cast<uint32_t*>(&lp0); lo.y = *reinterpret_cast<uint32_t*>(&lp1);
            *reinterpret_cast<uint2*>(&g_ch[base + h]) = ho;
            *reinterpret_cast<uint2*>(&g_cl[base + h]) = lo;
        }
    }
}

// ---------------------------------------------------------------------------
extern "C" void kernel_launch(void* const* d_in, const int* in_sizes, int n_in,
                              void* d_out, int out_size)
{
    const float* query = (const float*)d_in[0];
    const float* enc   = (const float*)d_in[1];
    const int*   lens  = (const int*)d_in[2];
    const float* W_s   = (const float*)d_in[3];
    const float* W_h   = (const float*)d_in[4];
    const float* v     = (const float*)d_in[5];
    const float* W_out = (const float*)d_in[6];
    float* out = (float*)d_out;

    float *TA, *TB;
    cudaGetSymbolAddress((void**)&TA,  g_TA);
    cudaGetSymbolAddress((void**)&TB,  g_TB);
    __nv_bfloat16 *qh,*ql,*eh,*el,*wsh,*wsl,*whh,*whl,*woh,*wol,*ch,*cl;
    cudaGetSymbolAddress((void**)&qh,  g_qh);  cudaGetSymbolAddress((void**)&ql,  g_ql);
    cudaGetSymbolAddress((void**)&eh,  g_eh);  cudaGetSymbolAddress((void**)&el,  g_el);
    cudaGetSymbolAddress((void**)&wsh, g_wsh); cudaGetSymbolAddress((void**)&wsl, g_wsl);
    cudaGetSymbolAddress((void**)&whh, g_whh); cudaGetSymbolAddress((void**)&whl, g_whl);
    cudaGetSymbolAddress((void**)&woh, g_woh); cudaGetSymbolAddress((void**)&wol, g_wol);
    cudaGetSymbolAddress((void**)&ch,  g_ch);  cudaGetSymbolAddress((void**)&cl,  g_cl);

    cudaFuncSetAttribute(attn_ctx_kernel,
                         cudaFuncAttributeMaxDynamicSharedMemorySize, SMEM_ATTN);
    cudaFuncSetAttribute(gemm_mma_epi,
                         cudaFuncAttributeMaxDynamicSharedMemorySize, GEMM_SMEM);

    const int TOT4 = N4_Q + N4_E + 2 * N4_WS + N4_WO;
    cvt_all<<<TOT4 / 256, 256>>>(query, enc, W_s, W_h, W_out,
                                 qh, ql, eh, el, wsh, wsl, whh, whl, woh, wol);

    // K1: TA = exp(2 * query @ W_s^T)
    gemm_mma_epi<<<dim3(Hh/64, BT/128), 256, GEMM_SMEM>>>(
        qh, ql, qh, ql, 512, wsh, wsl, TA, 512, Hh, 1);
    // K2: TB = exp(2 * enc @ W_h^T)
    gemm_mma_epi<<<dim3(Hh/64, (Bb*Ss)/128), 256, GEMM_SMEM>>>(
        eh, el, eh, el, 512, whh, whl, TB, 512, Hh, 1);
    // K3: energies + softmax + context (+ bf16 hi/lo emit of context)
    attn_ctx_kernel<<<dim3(Tt/16, Bb), 512, SMEM_ATTN>>>(enc, v, lens);
    // K4: out = tanh([context|query] @ W_out^T), K=1024
    gemm_mma_epi<<<dim3(Hh/64, BT/128), 256, GEMM_SMEM>>>(
        ch, cl, qh, ql, 512, woh, wol, out, 1024, Hh, 0);
}

// round 11
// speedup vs baseline: 2.1019x; 1.1780x over previous
#include <cuda_runtime.h>
#include <cuda_bf16.h>
#include <math.h>
#include <stdint.h>

#define Bb 8
#define Tt 256
#define Ss 256
#define Hh 512
#define BT (Bb*Tt)

// ------------------------- scratch (device globals) -------------------------
__device__ float g_TA[BT * Hh];       // exp(2 * query @ W_s^T)
__device__ float g_TB[Bb * Ss * Hh];  // exp(2 * enc   @ W_h^T)
__device__ float g_QW[BT * Hh];       // query @ Wo2^T

__device__ __nv_bfloat16 g_qh[BT * Hh],  g_ql[BT * Hh];
__device__ __nv_bfloat16 g_eh[Bb*Ss*Hh], g_el[Bb*Ss*Hh];
__device__ __nv_bfloat16 g_wsh[Hh*Hh],   g_wsl[Hh*Hh];
__device__ __nv_bfloat16 g_whh[Hh*Hh],   g_whl[Hh*Hh];
__device__ __nv_bfloat16 g_woh[Hh*2*Hh], g_wol[Hh*2*Hh];
__device__ __nv_bfloat16 g_awh[BT * Ss],   g_awl[BT * Ss];    // attn weights
__device__ __nv_bfloat16 g_EWth[Bb*Hh*Ss], g_EWtl[Bb*Hh*Ss];  // (enc@Wo1^T)^T

// ------------------------- helpers -------------------------
__device__ __forceinline__ uint32_t smem_u32(const void* p) {
    uint32_t a;
    asm("{ .reg .u64 t; cvta.to.shared.u64 t, %1; cvt.u32.u64 %0, t; }" : "=r"(a) : "l"(p));
    return a;
}

#define LDSM4(r, addr) \
    asm volatile("ldmatrix.sync.aligned.m8n8.x4.shared.b16 {%0,%1,%2,%3}, [%4];" \
        : "=r"((r)[0]), "=r"((r)[1]), "=r"((r)[2]), "=r"((r)[3]) : "r"(addr))

#define MMA16816(c, a, b) \
    asm volatile("mma.sync.aligned.m16n8k16.row.col.f32.bf16.bf16.f32 " \
        "{%0,%1,%2,%3}, {%4,%5,%6,%7}, {%8,%9}, {%0,%1,%2,%3};" \
        : "+f"((c)[0]), "+f"((c)[1]), "+f"((c)[2]), "+f"((c)[3]) \
        : "r"((a)[0]), "r"((a)[1]), "r"((a)[2]), "r"((a)[3]), "r"((b)[0]), "r"((b)[1]))

#define CP16(dst, src) \
    asm volatile("cp.async.cg.shared.global [%0], [%1], 16;" :: "r"(dst), "l"(src))
#define CP_COMMIT() asm volatile("cp.async.commit_group;")

#define RCPF(r, x) asm("rcp.approx.f32 %0, %1;" : "=f"(r) : "f"(x))

__device__ __forceinline__ void hilo_pack(float4 x, uint2& ho, uint2& lo)
{
    __nv_bfloat16 h0 = __float2bfloat16(x.x), h1 = __float2bfloat16(x.y);
    __nv_bfloat16 h2 = __float2bfloat16(x.z), h3 = __float2bfloat16(x.w);
    __nv_bfloat16 l0 = __float2bfloat16(x.x - __bfloat162float(h0));
    __nv_bfloat16 l1 = __float2bfloat16(x.y - __bfloat162float(h1));
    __nv_bfloat16 l2 = __float2bfloat16(x.z - __bfloat162float(h2));
    __nv_bfloat16 l3 = __float2bfloat16(x.w - __bfloat162float(h3));
    __nv_bfloat162 hp0 = __halves2bfloat162(h0, h1), hp1 = __halves2bfloat162(h2, h3);
    __nv_bfloat162 lp0 = __halves2bfloat162(l0, l1), lp1 = __halves2bfloat162(l2, l3);
    ho.x = *reinterpret_cast<uint32_t*>(&hp0); ho.y = *reinterpret_cast<uint32_t*>(&hp1);
    lo.x = *reinterpret_cast<uint32_t*>(&lp0); lo.y = *reinterpret_cast<uint32_t*>(&lp1);
}

// ------------------------- f32 -> bf16 hi/lo split (inputs) -----------------
__device__ __forceinline__ void cvt4(const float* __restrict__ x,
                                     __nv_bfloat16* __restrict__ hi,
                                     __nv_bfloat16* __restrict__ lo, int i)
{
    float4 v = reinterpret_cast<const float4*>(x)[i];
    uint2 ho, loo;
    hilo_pack(v, ho, loo);
    reinterpret_cast<uint2*>(hi)[i] = ho;
    reinterpret_cast<uint2*>(lo)[i] = loo;
}

#define N4_Q  (BT*Hh/4)
#define N4_E  (Bb*Ss*Hh/4)
#define N4_WS (Hh*Hh/4)
#define N4_WO (Hh*2*Hh/4)
__global__ __launch_bounds__(256) void cvt_all(
    const float* q, const float* e, const float* ws, const float* wh, const float* wo,
    __nv_bfloat16* qh, __nv_bfloat16* ql, __nv_bfloat16* eh, __nv_bfloat16* el,
    __nv_bfloat16* wsh, __nv_bfloat16* wsl, __nv_bfloat16* whh, __nv_bfloat16* whl,
    __nv_bfloat16* woh, __nv_bfloat16* wol)
{
    int i = blockIdx.x * blockDim.x + threadIdx.x;
    if (i < N4_Q)  { cvt4(q,  qh,  ql,  i); return; }  i -= N4_Q;
    if (i < N4_E)  { cvt4(e,  eh,  el,  i); return; }  i -= N4_E;
    if (i < N4_WS) { cvt4(ws, wsh, wsl, i); return; }  i -= N4_WS;
    if (i < N4_WS) { cvt4(wh, whh, whl, i); return; }  i -= N4_WS;
    if (i < N4_WO) { cvt4(wo, woh, wol, i); }
}

// ---------------------------------------------------------------------------
// HMMA bf16x3 GEMM, 2-stage cp.async pipeline.
// C[m][n] = epi( sum_k A[m][k] * W[n][k] ), A row stride astride, W wstride.
// Batched via blockIdx.z with element strides bsA/bsW/bsC.
// modes: 1 = exp(2x)->C ; 2 = bf16 hi/lo -> Chi,Clo ; 3 = tanh(x+QW)->C ;
//        4 = linear->C
// ---------------------------------------------------------------------------
#define OFF_AH 0
#define OFF_AL 10240
#define OFF_BH 20480
#define OFF_BL 25600
#define STG    30720
#define GEMM_SMEM (2*STG)

__global__ __launch_bounds__(256) void gemm_mma_epi(
    const __nv_bfloat16* __restrict__ Ah, const __nv_bfloat16* __restrict__ Al,
    int astride,
    const __nv_bfloat16* __restrict__ Wh, const __nv_bfloat16* __restrict__ Wl,
    int wstride,
    float* __restrict__ C, __nv_bfloat16* __restrict__ Chi,
    __nv_bfloat16* __restrict__ Clo, const float* __restrict__ QW,
    int K, int Nout, int mode, int bsA, int bsW, int bsC)
{
    extern __shared__ char smem[];
    const uint32_t sb = smem_u32(smem);

    const int bz = blockIdx.z;
    Ah += (size_t)bz * bsA; Al += (size_t)bz * bsA;
    Wh += (size_t)bz * bsW; Wl += (size_t)bz * bsW;
    const size_t cofs = (size_t)bz * bsC;

    const int tid = threadIdx.x;
    const int wid = tid >> 5, lane = tid & 31;
    const int wm = (wid & 3) * 32;
    const int wn = (wid >> 2) * 32;
    const int m0 = blockIdx.y * 128, n0 = blockIdx.x * 64;

    const int ar = tid >> 2;
    const int ac = (tid & 3) * 8;
    const int g  = lane >> 3;
    const int rr = lane & 7;

    float acc[2][4][4];
    #pragma unroll
    for (int mi = 0; mi < 2; mi++)
        #pragma unroll
        for (int ni = 0; ni < 4; ni++)
            #pragma unroll
            for (int r = 0; r < 4; r++) acc[mi][ni][r] = 0.0f;

    auto load_stage = [&](int kc, int stg) {
        const int k0 = kc * 32;
        const uint32_t base = sb + stg * STG;
        #pragma unroll
        for (int r = 0; r < 2; r++) {
            int row = ar + r * 64;
            size_t gidx = (size_t)(m0 + row) * astride + k0 + ac;
            CP16(base + OFF_AH + row * 80 + ac * 2, &Ah[gidx]);
            CP16(base + OFF_AL + row * 80 + ac * 2, &Al[gidx]);
        }
        size_t gw = (size_t)(n0 + ar) * wstride + k0 + ac;
        CP16(base + OFF_BH + ar * 80 + ac * 2, &Wh[gw]);
        CP16(base + OFF_BL + ar * 80 + ac * 2, &Wl[gw]);
    };

    auto compute = [&](int stg) {
        const uint32_t base = sb + stg * STG;
        #pragma unroll
        for (int ks = 0; ks < 32; ks += 16) {
            uint32_t ah[2][4], al[2][4], bh[4][2], bl[4][2];
            const int colb = (ks + (g >> 1) * 8) * 2;
            #pragma unroll
            for (int mi = 0; mi < 2; mi++) {
                int row = wm + mi * 16 + (g & 1) * 8 + rr;
                LDSM4(ah[mi], base + OFF_AH + row * 80 + colb);
                LDSM4(al[mi], base + OFF_AL + row * 80 + colb);
            }
            #pragma unroll
            for (int nb = 0; nb < 2; nb++) {
                int row = wn + nb * 16 + (g & 1) * 8 + rr;
                uint32_t t[4];
                LDSM4(t, base + OFF_BH + row * 80 + colb);
                bh[nb*2+0][0] = t[0]; bh[nb*2+0][1] = t[2];
                bh[nb*2+1][0] = t[1]; bh[nb*2+1][1] = t[3];
                LDSM4(t, base + OFF_BL + row * 80 + colb);
                bl[nb*2+0][0] = t[0]; bl[nb*2+0][1] = t[2];
                bl[nb*2+1][0] = t[1]; bl[nb*2+1][1] = t[3];
            }
            #pragma unroll
            for (int mi = 0; mi < 2; mi++)
                #pragma unroll
                for (int ni = 0; ni < 4; ni++) {
                    MMA16816(acc[mi][ni], ah[mi], bh[ni]);
                    MMA16816(acc[mi][ni], ah[mi], bl[ni]);
                    MMA16816(acc[mi][ni], al[mi], bh[ni]);
                }
        }
    };

    const int NC = K / 32;
    load_stage(0, 0);
    CP_COMMIT();
    for (int kc = 0; kc < NC; kc++) {
        if (kc + 1 < NC) {
            load_stage(kc + 1, (kc + 1) & 1);
            CP_COMMIT();
            asm volatile("cp.async.wait_group 1;");
        } else {
            asm volatile("cp.async.wait_group 0;");
        }
        __syncthreads();
        compute(kc & 1);
        __syncthreads();
    }

    #pragma unroll
    for (int mi = 0; mi < 2; mi++)
        #pragma unroll
        for (int ni = 0; ni < 4; ni++) {
            int row = m0 + wm + mi * 16 + (lane >> 2);
            int col = n0 + wn + ni * 8 + (lane & 3) * 2;
            float x0 = acc[mi][ni][0], x1 = acc[mi][ni][1];
            float x2 = acc[mi][ni][2], x3 = acc[mi][ni][3];
            if (mode == 1) {
                float2 v0 = { __expf(2.0f * x0), __expf(2.0f * x1) };
                float2 v1 = { __expf(2.0f * x2), __expf(2.0f * x3) };
                *reinterpret_cast<float2*>(&C[cofs + (size_t)row * Nout + col]) = v0;
                *reinterpret_cast<float2*>(&C[cofs + (size_t)(row + 8) * Nout + col]) = v1;
            } else if (mode == 2) {
                __nv_bfloat16 h0 = __float2bfloat16(x0), h1 = __float2bfloat16(x1);
                __nv_bfloat16 h2 = __float2bfloat16(x2), h3 = __float2bfloat16(x3);
                __nv_bfloat16 l0 = __float2bfloat16(x0 - __bfloat162float(h0));
                __nv_bfloat16 l1 = __float2bfloat16(x1 - __bfloat162float(h1));
                __nv_bfloat16 l2 = __float2bfloat16(x2 - __bfloat162float(h2));
                __nv_bfloat16 l3 = __float2bfloat16(x3 - __bfloat162float(h3));
                __nv_bfloat162 hp0 = __halves2bfloat162(h0, h1), hp1 = __halves2bfloat162(h2, h3);
                __nv_bfloat162 lp0 = __halves2bfloat162(l0, l1), lp1 = __halves2bfloat162(l2, l3);
                *reinterpret_cast<uint32_t*>(&Chi[cofs + (size_t)row * Nout + col]) = *reinterpret_cast<uint32_t*>(&hp0);
                *reinterpret_cast<uint32_t*>(&Chi[cofs + (size_t)(row + 8) * Nout + col]) = *reinterpret_cast<uint32_t*>(&hp1);
                *reinterpret_cast<uint32_t*>(&Clo[cofs + (size_t)row * Nout + col]) = *reinterpret_cast<uint32_t*>(&lp0);
                *reinterpret_cast<uint32_t*>(&Clo[cofs + (size_t)(row + 8) * Nout + col]) = *reinterpret_cast<uint32_t*>(&lp1);
            } else if (mode == 3) {
                float2 q0 = *reinterpret_cast<const float2*>(&QW[cofs + (size_t)row * Nout + col]);
                float2 q1 = *reinterpret_cast<const float2*>(&QW[cofs + (size_t)(row + 8) * Nout + col]);
                float2 v0 = { tanhf(x0 + q0.x), tanhf(x1 + q0.y) };
                float2 v1 = { tanhf(x2 + q1.x), tanhf(x3 + q1.y) };
                *reinterpret_cast<float2*>(&C[cofs + (size_t)row * Nout + col]) = v0;
                *reinterpret_cast<float2*>(&C[cofs + (size_t)(row + 8) * Nout + col]) = v1;
            } else {
                float2 v0 = { x0, x1 };
                float2 v1 = { x2, x3 };
                *reinterpret_cast<float2*>(&C[cofs + (size_t)row * Nout + col]) = v0;
                *reinterpret_cast<float2*>(&C[cofs + (size_t)(row + 8) * Nout + col]) = v1;
            }
        }
}

// ---------------------------------------------------------------------------
// K3: energies + softmax -> attn weights (bf16 hi/lo).
// 512 threads. Warp w: t-group tg=w>>3 (8 t), s-tile st=w&7 (lane = s).
// E staged in h-chunks of 64 (cp.async, double buffered); each E read serves
// 8 t-rows. en(t,s) = -2 * sum_h v_h / (Ea*Eb + 1)  (+const cancels).
// ---------------------------------------------------------------------------
#define CPAD 68
#define BUFSZ (272 * CPAD)          // 256 E rows + 16 qa rows
#define SMEM_ATTN ((2*BUFSZ + 512 + 16*256) * 4)

__global__ __launch_bounds__(512) void attn_kernel(
    const float* __restrict__ v, const int* __restrict__ lens)
{
    extern __shared__ float sm[];
    float* buf = sm;                 // 2 x BUFSZ
    float* vb  = sm + 2 * BUFSZ;     // 512
    float* en  = vb + 512;           // 16 x 256

    const uint32_t sb = smem_u32(sm);
    const int tid  = threadIdx.x;
    const int w    = tid >> 5;
    const int lane = tid & 31;
    const int stile = w & 7;
    const int tg    = w >> 3;
    const int b  = blockIdx.y;
    const int t0 = blockIdx.x * 16;
    const int len = lens[b];

    if (tid < 128)
        *reinterpret_cast<float4*>(&vb[tid * 4]) =
            *reinterpret_cast<const float4*>(&v[tid * 4]);

    auto load_chunk = [&](int hc, int bb) {
        const uint32_t base = sb + bb * BUFSZ * 4;
        #pragma unroll
        for (int k = 0; k < 8; k++) {            // E: 256 rows x 16 float4
            int idx = tid + k * 512;
            int row = idx >> 4, c4 = idx & 15;
            CP16(base + (row * CPAD + c4 * 4) * 4,
                 &g_TB[(size_t)(b * Ss + row) * Hh + hc * 64 + c4 * 4]);
        }
        if (tid < 256) {                         // qa: 16 rows x 16 float4
            int row = tid >> 4, c4 = tid & 15;
            CP16(base + ((256 + row) * CPAD + c4 * 4) * 4,
                 &g_TA[(size_t)(b * Tt + t0 + row) * Hh + hc * 64 + c4 * 4]);
        }
    };

    float acc[8];
    #pragma unroll
    for (int j = 0; j < 8; j++) acc[j] = 0.0f;

    load_chunk(0, 0);
    CP_COMMIT();
    for (int hc = 0; hc < 8; hc++) {
        if (hc + 1 < 8) {
            load_chunk(hc + 1, (hc + 1) & 1);
            CP_COMMIT();
            asm volatile("cp.async.wait_group 1;");
        } else {
            asm volatile("cp.async.wait_group 0;");
        }
        __syncthreads();

        const float* eb = buf + (hc & 1) * BUFSZ;
        const float* qa = eb + 256 * CPAD;
        const float* erow = eb + (stile * 32 + lane) * CPAD;
        const float* vc = vb + hc * 64;
        const float* qg = qa + tg * 8 * CPAD;

        #pragma unroll 2
        for (int h4 = 0; h4 < 16; h4++) {
            float4 E = *reinterpret_cast<const float4*>(&erow[h4 * 4]);
            float4 V = *reinterpret_cast<const float4*>(&vc[h4 * 4]);
            #pragma unroll
            for (int j = 0; j < 8; j++) {
                float4 A = *reinterpret_cast<const float4*>(&qg[j * CPAD + h4 * 4]);
                float d0 = fmaf(A.x, E.x, 1.0f);
                float d1 = fmaf(A.y, E.y, 1.0f);
                float d2 = fmaf(A.z, E.z, 1.0f);
                float d3 = fmaf(A.w, E.w, 1.0f);
                float n01 = fmaf(V.y, d0, V.x * d1);
                float n23 = fmaf(V.w, d2, V.z * d3);
                float p01 = d0 * d1, p23 = d2 * d3;
                float r01, r23;
                RCPF(r01, p01); RCPF(r23, p23);
                acc[j] = fmaf(n01, r01, acc[j]);
                acc[j] = fmaf(n23, r23, acc[j]);
            }
        }
        __syncthreads();
    }

    // write energies (masked)
    {
        int s = stile * 32 + lane;
        float mval = (s < len) ? 0.0f : -INFINITY;
        #pragma unroll
        for (int j = 0; j < 8; j++) {
            int t = tg * 8 + j;
            en[t * 256 + s] = (s < len) ? (-2.0f * acc[j]) : mval;
        }
    }
    __syncthreads();

    // softmax: warp w handles row t=w (w < 16)
    {
        float e[8];
        float m = -INFINITY;
        #pragma unroll
        for (int j = 0; j < 8; j++) {
            e[j] = en[w * 256 + lane + 32 * j];
            m = fmaxf(m, e[j]);
        }
        #pragma unroll
        for (int o = 16; o; o >>= 1) m = fmaxf(m, __shfl_xor_sync(0xffffffffu, m, o));
        float sum = 0.0f;
        #pragma unroll
        for (int j = 0; j < 8; j++) { e[j] = __expf(e[j] - m); sum += e[j]; }
        #pragma unroll
        for (int o = 16; o; o >>= 1) sum += __shfl_xor_sync(0xffffffffu, sum, o);
        float rs; RCPF(rs, sum);
        #pragma unroll
        for (int j = 0; j < 8; j++) en[w * 256 + lane + 32 * j] = e[j] * rs;
    }
    __syncthreads();

    // emit weights as bf16 hi/lo: 4096 f32 = 1024 float4, 2 per thread
    #pragma unroll
    for (int k = 0; k < 2; k++) {
        int i = tid + k * 512;
        int row = i >> 6, c4 = i & 63;
        float4 x = *reinterpret_cast<const float4*>(&en[row * 256 + c4 * 4]);
        uint2 ho, lo;
        hilo_pack(x, ho, lo);
        size_t gidx = (size_t)(b * Tt + t0 + row) * Ss + c4 * 4;
        *reinterpret_cast<uint2*>(&g_awh[gidx]) = ho;
        *reinterpret_cast<uint2*>(&g_awl[gidx]) = lo;
    }
}

// ---------------------------------------------------------------------------
extern "C" void kernel_launch(void* const* d_in, const int* in_sizes, int n_in,
                              void* d_out, int out_size)
{
    const float* query = (const float*)d_in[0];
    const float* enc   = (const float*)d_in[1];
    const int*   lens  = (const int*)d_in[2];
    const float* W_s   = (const float*)d_in[3];
    const float* W_h   = (const float*)d_in[4];
    const float* v     = (const float*)d_in[5];
    const float* W_out = (const float*)d_in[6];
    float* out = (float*)d_out;

    float *TA, *TB, *QW;
    cudaGetSymbolAddress((void**)&TA, g_TA);
    cudaGetSymbolAddress((void**)&TB, g_TB);
    cudaGetSymbolAddress((void**)&QW, g_QW);
    __nv_bfloat16 *qh,*ql,*eh,*el,*wsh,*wsl,*whh,*whl,*woh,*wol,*awh,*awl,*EWth,*EWtl;
    cudaGetSymbolAddress((void**)&qh,  g_qh);  cudaGetSymbolAddress((void**)&ql,  g_ql);
    cudaGetSymbolAddress((void**)&eh,  g_eh);  cudaGetSymbolAddress((void**)&el,  g_el);
    cudaGetSymbolAddress((void**)&wsh, g_wsh); cudaGetSymbolAddress((void**)&wsl, g_wsl);
    cudaGetSymbolAddress((void**)&whh, g_whh); cudaGetSymbolAddress((void**)&whl, g_whl);
    cudaGetSymbolAddress((void**)&woh, g_woh); cudaGetSymbolAddress((void**)&wol, g_wol);
    cudaGetSymbolAddress((void**)&awh, g_awh); cudaGetSymbolAddress((void**)&awl, g_awl);
    cudaGetSymbolAddress((void**)&EWth, g_EWth); cudaGetSymbolAddress((void**)&EWtl, g_EWtl);

    cudaFuncSetAttribute(attn_kernel,
                         cudaFuncAttributeMaxDynamicSharedMemorySize, SMEM_ATTN);
    cudaFuncSetAttribute(gemm_mma_epi,
                         cudaFuncAttributeMaxDynamicSharedMemorySize, GEMM_SMEM);

    const int TOT4 = N4_Q + N4_E + 2 * N4_WS + N4_WO;
    cvt_all<<<TOT4 / 256, 256>>>(query, enc, W_s, W_h, W_out,
                                 qh, ql, eh, el, wsh, wsl, whh, whl, woh, wol);

    // K1: TA = exp(2 * query @ W_s^T)    M=2048 N=512 K=512
    gemm_mma_epi<<<dim3(8, 16, 1), 256, GEMM_SMEM>>>(
        qh, ql, 512, wsh, wsl, 512, TA, nullptr, nullptr, nullptr,
        512, 512, 1, 0, 0, 0);
    // K2: TB = exp(2 * enc @ W_h^T)
    gemm_mma_epi<<<dim3(8, 16, 1), 256, GEMM_SMEM>>>(
        eh, el, 512, whh, whl, 512, TB, nullptr, nullptr, nullptr,
        512, 512, 1, 0, 0, 0);
    // K1b: QW = query @ Wo2^T  (Wo2 = W_out cols 512..1023)
    gemm_mma_epi<<<dim3(8, 16, 1), 256, GEMM_SMEM>>>(
        qh, ql, 512, woh + 512, wol + 512, 1024, QW, nullptr, nullptr, nullptr,
        512, 512, 4, 0, 0, 0);
    // K2b: EWt[b] = Wo1 @ enc[b]^T  -> bf16 hi/lo   M=512 N=256 K=512, batch 8
    gemm_mma_epi<<<dim3(4, 4, 8), 256, GEMM_SMEM>>>(
        woh, wol, 1024, eh, el, 512, TA /*unused*/, EWth, EWtl, nullptr,
        512, 256, 2, 0, Ss * Hh, Hh * Ss);
    // K3: energies + softmax -> attn weights bf16 hi/lo
    attn_kernel<<<dim3(Tt / 16, Bb), 512, SMEM_ATTN>>>(v, lens);
    // K5: out[b] = tanh(attnw[b] @ EWt[b]^T + QW)   M=256 N=512 K=256, batch 8
    gemm_mma_epi<<<dim3(8, 2, 8), 256, GEMM_SMEM>>>(
        awh, awl, 256, EWth, EWtl, 256, out, nullptr, nullptr, QW,
        256, 512, 3, Tt * Ss, Hh * Ss, Tt * Hh);
}

// round 12
// speedup vs baseline: 2.2095x; 1.0512x over previous
#include <cuda_runtime.h>
#include <cuda_bf16.h>
#include <math.h>
#include <stdint.h>

#define Bb 8
#define Tt 256
#define Ss 256
#define Hh 512
#define BT (Bb*Tt)

// ------------------------- scratch (device globals) -------------------------
__device__ float g_TA[BT * Hh];       // exp(2 * query @ W_s^T)
__device__ float g_TB[Bb * Ss * Hh];  // exp(2 * enc   @ W_h^T)
__device__ float g_QW[BT * Hh];       // query @ Wo2^T

__device__ __nv_bfloat16 g_qh[BT * Hh],    g_ql[BT * Hh];
__device__ __nv_bfloat16 g_eh[Bb*Ss*Hh],   g_el[Bb*Ss*Hh];
__device__ __nv_bfloat16 g_wcath[1024*Hh], g_wcatl[1024*Hh];  // [W_s ; Wo2]
__device__ __nv_bfloat16 g_whh[Hh*Hh],     g_whl[Hh*Hh];
__device__ __nv_bfloat16 g_wo1h[Hh*Hh],    g_wo1l[Hh*Hh];     // Wo1 compact
__device__ __nv_bfloat16 g_awh[BT * Ss],   g_awl[BT * Ss];    // attn weights
__device__ __nv_bfloat16 g_EWth[Bb*Hh*Ss], g_EWtl[Bb*Hh*Ss];  // (enc@Wo1^T)^T

// ------------------------- helpers -------------------------
__device__ __forceinline__ uint32_t smem_u32(const void* p) {
    uint32_t a;
    asm("{ .reg .u64 t; cvta.to.shared.u64 t, %1; cvt.u32.u64 %0, t; }" : "=r"(a) : "l"(p));
    return a;
}

#define LDSM4(r, addr) \
    asm volatile("ldmatrix.sync.aligned.m8n8.x4.shared.b16 {%0,%1,%2,%3}, [%4];" \
        : "=r"((r)[0]), "=r"((r)[1]), "=r"((r)[2]), "=r"((r)[3]) : "r"(addr))

#define MMA16816(c, a, b) \
    asm volatile("mma.sync.aligned.m16n8k16.row.col.f32.bf16.bf16.f32 " \
        "{%0,%1,%2,%3}, {%4,%5,%6,%7}, {%8,%9}, {%0,%1,%2,%3};" \
        : "+f"((c)[0]), "+f"((c)[1]), "+f"((c)[2]), "+f"((c)[3]) \
        : "r"((a)[0]), "r"((a)[1]), "r"((a)[2]), "r"((a)[3]), "r"((b)[0]), "r"((b)[1]))

#define CP16(dst, src) \
    asm volatile("cp.async.cg.shared.global [%0], [%1], 16;" :: "r"(dst), "l"(src))
#define CP_COMMIT() asm volatile("cp.async.commit_group;")

#define RCPF(r, x) asm("rcp.approx.f32 %0, %1;" : "=f"(r) : "f"(x))

__device__ __forceinline__ void hilo_pack(float4 x, uint2& ho, uint2& lo)
{
    __nv_bfloat16 h0 = __float2bfloat16(x.x), h1 = __float2bfloat16(x.y);
    __nv_bfloat16 h2 = __float2bfloat16(x.z), h3 = __float2bfloat16(x.w);
    __nv_bfloat16 l0 = __float2bfloat16(x.x - __bfloat162float(h0));
    __nv_bfloat16 l1 = __float2bfloat16(x.y - __bfloat162float(h1));
    __nv_bfloat16 l2 = __float2bfloat16(x.z - __bfloat162float(h2));
    __nv_bfloat16 l3 = __float2bfloat16(x.w - __bfloat162float(h3));
    __nv_bfloat162 hp0 = __halves2bfloat162(h0, h1), hp1 = __halves2bfloat162(h2, h3);
    __nv_bfloat162 lp0 = __halves2bfloat162(l0, l1), lp1 = __halves2bfloat162(l2, l3);
    ho.x = *reinterpret_cast<uint32_t*>(&hp0); ho.y = *reinterpret_cast<uint32_t*>(&hp1);
    lo.x = *reinterpret_cast<uint32_t*>(&lp0); lo.y = *reinterpret_cast<uint32_t*>(&lp1);
}

__device__ __forceinline__ void cvt4(const float* __restrict__ x,
                                     __nv_bfloat16* __restrict__ hi,
                                     __nv_bfloat16* __restrict__ lo, int i)
{
    float4 v = reinterpret_cast<const float4*>(x)[i];
    uint2 ho, loo;
    hilo_pack(v, ho, loo);
    reinterpret_cast<uint2*>(hi)[i] = ho;
    reinterpret_cast<uint2*>(lo)[i] = loo;
}

#define N4_Q  (BT*Hh/4)
#define N4_E  (Bb*Ss*Hh/4)
#define N4_WS (Hh*Hh/4)
#define N4_WO (Hh*2*Hh/4)
// Converts: query, enc, W_s -> wcat rows 0-511, W_h, W_out -> (wo1 | wcat rows 512-1023)
__global__ __launch_bounds__(256) void cvt_all(
    const float* q, const float* e, const float* ws, const float* wh, const float* wo,
    __nv_bfloat16* qh, __nv_bfloat16* ql, __nv_bfloat16* eh, __nv_bfloat16* el,
    __nv_bfloat16* wcath, __nv_bfloat16* wcatl,
    __nv_bfloat16* whh, __nv_bfloat16* whl,
    __nv_bfloat16* wo1h, __nv_bfloat16* wo1l)
{
    int i = blockIdx.x * blockDim.x + threadIdx.x;
    if (i < N4_Q)  { cvt4(q,  qh,  ql,  i); return; }  i -= N4_Q;
    if (i < N4_E)  { cvt4(e,  eh,  el,  i); return; }  i -= N4_E;
    if (i < N4_WS) { cvt4(ws, wcath, wcatl, i); return; }  i -= N4_WS;
    if (i < N4_WS) { cvt4(wh, whh, whl, i); return; }  i -= N4_WS;
    if (i < N4_WO) {
        int r = i >> 8, c4 = i & 255;    // W_out row, float4 col
        float4 v = reinterpret_cast<const float4*>(wo)[i];
        uint2 ho, lo;
        hilo_pack(v, ho, lo);
        if (c4 < 128) {                  // Wo1 -> compact [512][512]
            int di = r * 128 + c4;
            reinterpret_cast<uint2*>(wo1h)[di] = ho;
            reinterpret_cast<uint2*>(wo1l)[di] = lo;
        } else {                         // Wo2 -> wcat rows 512-1023
            int di = (512 + r) * 128 + (c4 - 128);
            reinterpret_cast<uint2*>(wcath)[di] = ho;
            reinterpret_cast<uint2*>(wcatl)[di] = lo;
        }
    }
}

// ---------------------------------------------------------------------------
// HMMA bf16x3 GEMM, 2-stage cp.async pipeline, batched via blockIdx.z.
// modes: 1 exp(2x)->C ; 2 bf16 hi/lo -> Chi,Clo ; 3 tanh(x+QW)->C ;
//        4 linear->C ; 5 split: n0<512 exp->C, else linear->C2 (col-512)
// lenmodes: 1 skip block if (m0%256)>=len[m0>>8] ;
//           2 skip block if (n0%256)>=ceil32(len[bz]) ;
//           3 clamp K chunks to ceil(len[bz]/32)
// ---------------------------------------------------------------------------
#define OFF_AH 0
#define OFF_AL 10240
#define OFF_BH 20480
#define OFF_BL 25600
#define STG    30720
#define GEMM_SMEM (2*STG)

__global__ __launch_bounds__(256) void gemm_mma_epi(
    const __nv_bfloat16* __restrict__ Ah, const __nv_bfloat16* __restrict__ Al,
    int astride,
    const __nv_bfloat16* __restrict__ Wh, const __nv_bfloat16* __restrict__ Wl,
    int wstride,
    float* __restrict__ C, float* __restrict__ C2,
    __nv_bfloat16* __restrict__ Chi, __nv_bfloat16* __restrict__ Clo,
    const float* __restrict__ QW,
    const int* __restrict__ lens, int lenmode,
    int K, int Nout, int mode, int bsA, int bsW, int bsC)
{
    extern __shared__ char smem[];
    const uint32_t sb = smem_u32(smem);

    const int bz = blockIdx.z;
    const int m0 = blockIdx.y * 128, n0 = blockIdx.x * 64;

    if (lenmode == 1) {
        if ((m0 & 255) >= lens[m0 >> 8]) return;
    } else if (lenmode == 2) {
        int L = (lens[bz] + 31) & ~31;
        if ((n0 & 255) >= L) return;
    }
    int NC = K / 32;
    if (lenmode == 3) {
        int c = (lens[bz] + 31) >> 5;
        if (c < NC) NC = c;
    }

    Ah += (size_t)bz * bsA; Al += (size_t)bz * bsA;
    Wh += (size_t)bz * bsW; Wl += (size_t)bz * bsW;
    const size_t cofs = (size_t)bz * bsC;

    const int tid = threadIdx.x;
    const int wid = tid >> 5, lane = tid & 31;
    const int wm = (wid & 3) * 32;
    const int wn = (wid >> 2) * 32;

    const int ar = tid >> 2;
    const int ac = (tid & 3) * 8;
    const int g  = lane >> 3;
    const int rr = lane & 7;

    float acc[2][4][4];
    #pragma unroll
    for (int mi = 0; mi < 2; mi++)
        #pragma unroll
        for (int ni = 0; ni < 4; ni++)
            #pragma unroll
            for (int r = 0; r < 4; r++) acc[mi][ni][r] = 0.0f;

    auto load_stage = [&](int kc, int stg) {
        const int k0 = kc * 32;
        const uint32_t base = sb + stg * STG;
        #pragma unroll
        for (int r = 0; r < 2; r++) {
            int row = ar + r * 64;
            size_t gidx = (size_t)(m0 + row) * astride + k0 + ac;
            CP16(base + OFF_AH + row * 80 + ac * 2, &Ah[gidx]);
            CP16(base + OFF_AL + row * 80 + ac * 2, &Al[gidx]);
        }
        size_t gw = (size_t)(n0 + ar) * wstride + k0 + ac;
        CP16(base + OFF_BH + ar * 80 + ac * 2, &Wh[gw]);
        CP16(base + OFF_BL + ar * 80 + ac * 2, &Wl[gw]);
    };

    auto compute = [&](int stg) {
        const uint32_t base = sb + stg * STG;
        #pragma unroll
        for (int ks = 0; ks < 32; ks += 16) {
            uint32_t ah[2][4], al[2][4], bh[4][2], bl[4][2];
            const int colb = (ks + (g >> 1) * 8) * 2;
            #pragma unroll
            for (int mi = 0; mi < 2; mi++) {
                int row = wm + mi * 16 + (g & 1) * 8 + rr;
                LDSM4(ah[mi], base + OFF_AH + row * 80 + colb);
                LDSM4(al[mi], base + OFF_AL + row * 80 + colb);
            }
            #pragma unroll
            for (int nb = 0; nb < 2; nb++) {
                int row = wn + nb * 16 + (g & 1) * 8 + rr;
                uint32_t t[4];
                LDSM4(t, base + OFF_BH + row * 80 + colb);
                bh[nb*2+0][0] = t[0]; bh[nb*2+0][1] = t[2];
                bh[nb*2+1][0] = t[1]; bh[nb*2+1][1] = t[3];
                LDSM4(t, base + OFF_BL + row * 80 + colb);
                bl[nb*2+0][0] = t[0]; bl[nb*2+0][1] = t[2];
                bl[nb*2+1][0] = t[1]; bl[nb*2+1][1] = t[3];
            }
            #pragma unroll
            for (int mi = 0; mi < 2; mi++)
                #pragma unroll
                for (int ni = 0; ni < 4; ni++) {
                    MMA16816(acc[mi][ni], ah[mi], bh[ni]);
                    MMA16816(acc[mi][ni], ah[mi], bl[ni]);
                    MMA16816(acc[mi][ni], al[mi], bh[ni]);
                }
        }
    };

    load_stage(0, 0);
    CP_COMMIT();
    for (int kc = 0; kc < NC; kc++) {
        if (kc + 1 < NC) {
            load_stage(kc + 1, (kc + 1) & 1);
            CP_COMMIT();
            asm volatile("cp.async.wait_group 1;");
        } else {
            asm volatile("cp.async.wait_group 0;");
        }
        __syncthreads();
        compute(kc & 1);
        __syncthreads();
    }

    #pragma unroll
    for (int mi = 0; mi < 2; mi++)
        #pragma unroll
        for (int ni = 0; ni < 4; ni++) {
            int row = m0 + wm + mi * 16 + (lane >> 2);
            int col = n0 + wn + ni * 8 + (lane & 3) * 2;
            float x0 = acc[mi][ni][0], x1 = acc[mi][ni][1];
            float x2 = acc[mi][ni][2], x3 = acc[mi][ni][3];
            if (mode == 1 || (mode == 5 && n0 < 512)) {
                float2 v0 = { __expf(2.0f * x0), __expf(2.0f * x1) };
                float2 v1 = { __expf(2.0f * x2), __expf(2.0f * x3) };
                *reinterpret_cast<float2*>(&C[cofs + (size_t)row * Nout + col]) = v0;
                *reinterpret_cast<float2*>(&C[cofs + (size_t)(row + 8) * Nout + col]) = v1;
            } else if (mode == 5) {
                int cq = col - 512;
                float2 v0 = { x0, x1 };
                float2 v1 = { x2, x3 };
                *reinterpret_cast<float2*>(&C2[(size_t)row * Nout + cq]) = v0;
                *reinterpret_cast<float2*>(&C2[(size_t)(row + 8) * Nout + cq]) = v1;
            } else if (mode == 2) {
                __nv_bfloat16 h0 = __float2bfloat16(x0), h1 = __float2bfloat16(x1);
                __nv_bfloat16 h2 = __float2bfloat16(x2), h3 = __float2bfloat16(x3);
                __nv_bfloat16 l0 = __float2bfloat16(x0 - __bfloat162float(h0));
                __nv_bfloat16 l1 = __float2bfloat16(x1 - __bfloat162float(h1));
                __nv_bfloat16 l2 = __float2bfloat16(x2 - __bfloat162float(h2));
                __nv_bfloat16 l3 = __float2bfloat16(x3 - __bfloat162float(h3));
                __nv_bfloat162 hp0 = __halves2bfloat162(h0, h1), hp1 = __halves2bfloat162(h2, h3);
                __nv_bfloat162 lp0 = __halves2bfloat162(l0, l1), lp1 = __halves2bfloat162(l2, l3);
                *reinterpret_cast<uint32_t*>(&Chi[cofs + (size_t)row * Nout + col]) = *reinterpret_cast<uint32_t*>(&hp0);
                *reinterpret_cast<uint32_t*>(&Chi[cofs + (size_t)(row + 8) * Nout + col]) = *reinterpret_cast<uint32_t*>(&hp1);
                *reinterpret_cast<uint32_t*>(&Clo[cofs + (size_t)row * Nout + col]) = *reinterpret_cast<uint32_t*>(&lp0);
                *reinterpret_cast<uint32_t*>(&Clo[cofs + (size_t)(row + 8) * Nout + col]) = *reinterpret_cast<uint32_t*>(&lp1);
            } else if (mode == 3) {
                float2 q0 = *reinterpret_cast<const float2*>(&QW[cofs + (size_t)row * Nout + col]);
                float2 q1 = *reinterpret_cast<const float2*>(&QW[cofs + (size_t)(row + 8) * Nout + col]);
                float2 v0 = { tanhf(x0 + q0.x), tanhf(x1 + q0.y) };
                float2 v1 = { tanhf(x2 + q1.x), tanhf(x3 + q1.y) };
                *reinterpret_cast<float2*>(&C[cofs + (size_t)row * Nout + col]) = v0;
                *reinterpret_cast<float2*>(&C[cofs + (size_t)(row + 8) * Nout + col]) = v1;
            } else {
                float2 v0 = { x0, x1 };
                float2 v1 = { x2, x3 };
                *reinterpret_cast<float2*>(&C[cofs + (size_t)row * Nout + col]) = v0;
                *reinterpret_cast<float2*>(&C[cofs + (size_t)(row + 8) * Nout + col]) = v1;
            }
        }
}

// ---------------------------------------------------------------------------
// K3: energies + softmax -> attn weights (bf16 hi/lo). Length-aware:
// masked s-tiles skip compute; E-row loads clamped to ceil32(len).
// ---------------------------------------------------------------------------
#define CPAD 68
#define BUFSZ (272 * CPAD)
#define SMEM_ATTN ((2*BUFSZ + 512 + 16*256) * 4)

__global__ __launch_bounds__(512) void attn_kernel(
    const float* __restrict__ v, const int* __restrict__ lens)
{
    extern __shared__ float sm[];
    float* buf = sm;
    float* vb  = sm + 2 * BUFSZ;
    float* en  = vb + 512;

    const uint32_t sb = smem_u32(sm);
    const int tid  = threadIdx.x;
    const int w    = tid >> 5;
    const int lane = tid & 31;
    const int stile = w & 7;
    const int tg    = w >> 3;
    const int b  = blockIdx.y;
    const int t0 = blockIdx.x * 16;
    const int len = lens[b];
    const int lenc = (len + 31) & ~31;

    if (tid < 128)
        *reinterpret_cast<float4*>(&vb[tid * 4]) =
            *reinterpret_cast<const float4*>(&v[tid * 4]);

    auto load_chunk = [&](int hc, int bb) {
        const uint32_t base = sb + bb * BUFSZ * 4;
        #pragma unroll
        for (int k = 0; k < 8; k++) {
            int idx = tid + k * 512;
            int row = idx >> 4, c4 = idx & 15;
            if (row < lenc)
                CP16(base + (row * CPAD + c4 * 4) * 4,
                     &g_TB[(size_t)(b * Ss + row) * Hh + hc * 64 + c4 * 4]);
        }
        if (tid < 256) {
            int row = tid >> 4, c4 = tid & 15;
            CP16(base + ((256 + row) * CPAD + c4 * 4) * 4,
                 &g_TA[(size_t)(b * Tt + t0 + row) * Hh + hc * 64 + c4 * 4]);
        }
    };

    float acc[8];
    #pragma unroll
    for (int j = 0; j < 8; j++) acc[j] = 0.0f;

    const bool active = (stile * 32) < len;

    load_chunk(0, 0);
    CP_COMMIT();
    for (int hc = 0; hc < 8; hc++) {
        if (hc + 1 < 8) {
            load_chunk(hc + 1, (hc + 1) & 1);
            CP_COMMIT();
            asm volatile("cp.async.wait_group 1;");
        } else {
            asm volatile("cp.async.wait_group 0;");
        }
        __syncthreads();

        if (active) {
            const float* eb = buf + (hc & 1) * BUFSZ;
            const float* qa = eb + 256 * CPAD;
            const float* erow = eb + (stile * 32 + lane) * CPAD;
            const float* vc = vb + hc * 64;
            const float* qg = qa + tg * 8 * CPAD;

            #pragma unroll 2
            for (int h4 = 0; h4 < 16; h4++) {
                float4 E = *reinterpret_cast<const float4*>(&erow[h4 * 4]);
                float4 V = *reinterpret_cast<const float4*>(&vc[h4 * 4]);
                #pragma unroll
                for (int j = 0; j < 8; j++) {
                    float4 A = *reinterpret_cast<const float4*>(&qg[j * CPAD + h4 * 4]);
                    float d0 = fmaf(A.x, E.x, 1.0f);
                    float d1 = fmaf(A.y, E.y, 1.0f);
                    float d2 = fmaf(A.z, E.z, 1.0f);
                    float d3 = fmaf(A.w, E.w, 1.0f);
                    float n01 = fmaf(V.y, d0, V.x * d1);
                    float n23 = fmaf(V.w, d2, V.z * d3);
                    float p01 = d0 * d1, p23 = d2 * d3;
                    float r01, r23;
                    RCPF(r01, p01); RCPF(r23, p23);
                    acc[j] = fmaf(n01, r01, acc[j]);
                    acc[j] = fmaf(n23, r23, acc[j]);
                }
            }
        }
        __syncthreads();
    }

    {
        int s = stile * 32 + lane;
        #pragma unroll
        for (int j = 0; j < 8; j++) {
            int t = tg * 8 + j;
            en[t * 256 + s] = (s < len) ? (-2.0f * acc[j]) : -INFINITY;
        }
    }
    __syncthreads();

    {
        float e[8];
        float m = -INFINITY;
        #pragma unroll
        for (int j = 0; j < 8; j++) {
            e[j] = en[w * 256 + lane + 32 * j];
            m = fmaxf(m, e[j]);
        }
        #pragma unroll
        for (int o = 16; o; o >>= 1) m = fmaxf(m, __shfl_xor_sync(0xffffffffu, m, o));
        float sum = 0.0f;
        #pragma unroll
        for (int j = 0; j < 8; j++) { e[j] = __expf(e[j] - m); sum += e[j]; }
        #pragma unroll
        for (int o = 16; o; o >>= 1) sum += __shfl_xor_sync(0xffffffffu, sum, o);
        float rs; RCPF(rs, sum);
        #pragma unroll
        for (int j = 0; j < 8; j++) en[w * 256 + lane + 32 * j] = e[j] * rs;
    }
    __syncthreads();

    #pragma unroll
    for (int k = 0; k < 2; k++) {
        int i = tid + k * 512;
        int row = i >> 6, c4 = i & 63;
        float4 x = *reinterpret_cast<const float4*>(&en[row * 256 + c4 * 4]);
        uint2 ho, lo;
        hilo_pack(x, ho, lo);
        size_t gidx = (size_t)(b * Tt + t0 + row) * Ss + c4 * 4;
        *reinterpret_cast<uint2*>(&g_awh[gidx]) = ho;
        *reinterpret_cast<uint2*>(&g_awl[gidx]) = lo;
    }
}

// ---------------------------------------------------------------------------
extern "C" void kernel_launch(void* const* d_in, const int* in_sizes, int n_in,
                              void* d_out, int out_size)
{
    const float* query = (const float*)d_in[0];
    const float* enc   = (const float*)d_in[1];
    const int*   lens  = (const int*)d_in[2];
    const float* W_s   = (const float*)d_in[3];
    const float* W_h   = (const float*)d_in[4];
    const float* v     = (const float*)d_in[5];
    const float* W_out = (const float*)d_in[6];
    float* out = (float*)d_out;

    float *TA, *TB, *QW;
    cudaGetSymbolAddress((void**)&TA, g_TA);
    cudaGetSymbolAddress((void**)&TB, g_TB);
    cudaGetSymbolAddress((void**)&QW, g_QW);
    __nv_bfloat16 *qh,*ql,*eh,*el,*wcath,*wcatl,*whh,*whl,*wo1h,*wo1l,*awh,*awl,*EWth,*EWtl;
    cudaGetSymbolAddress((void**)&qh,  g_qh);  cudaGetSymbolAddress((void**)&ql,  g_ql);
    cudaGetSymbolAddress((void**)&eh,  g_eh);  cudaGetSymbolAddress((void**)&el,  g_el);
    cudaGetSymbolAddress((void**)&wcath, g_wcath); cudaGetSymbolAddress((void**)&wcatl, g_wcatl);
    cudaGetSymbolAddress((void**)&whh, g_whh); cudaGetSymbolAddress((void**)&whl, g_whl);
    cudaGetSymbolAddress((void**)&wo1h, g_wo1h); cudaGetSymbolAddress((void**)&wo1l, g_wo1l);
    cudaGetSymbolAddress((void**)&awh, g_awh); cudaGetSymbolAddress((void**)&awl, g_awl);
    cudaGetSymbolAddress((void**)&EWth, g_EWth); cudaGetSymbolAddress((void**)&EWtl, g_EWtl);

    cudaFuncSetAttribute(attn_kernel,
                         cudaFuncAttributeMaxDynamicSharedMemorySize, SMEM_ATTN);
    cudaFuncSetAttribute(gemm_mma_epi,
                         cudaFuncAttributeMaxDynamicSharedMemorySize, GEMM_SMEM);

    const int TOT4 = N4_Q + N4_E + 2 * N4_WS + N4_WO;
    cvt_all<<<TOT4 / 256, 256>>>(query, enc, W_s, W_h, W_out,
                                 qh, ql, eh, el, wcath, wcatl, whh, whl, wo1h, wo1l);

    // G1: n<512 -> TA = exp(2*q@Ws^T); n>=512 -> QW = q@Wo2^T  (M=2048,N=1024,K=512)
    gemm_mma_epi<<<dim3(16, 16, 1), 256, GEMM_SMEM>>>(
        qh, ql, 512, wcath, wcatl, 512, TA, QW, nullptr, nullptr, nullptr,
        nullptr, 0, 512, 512, 5, 0, 0, 0);
    // K2: TB = exp(2 * enc @ W_h^T), skip fully-masked row blocks
    gemm_mma_epi<<<dim3(8, 16, 1), 256, GEMM_SMEM>>>(
        eh, el, 512, whh, whl, 512, TB, nullptr, nullptr, nullptr, nullptr,
        lens, 1, 512, 512, 1, 0, 0, 0);
    // K2b: EWt[b] = Wo1 @ enc[b]^T -> bf16 hi/lo, skip masked s blocks
    gemm_mma_epi<<<dim3(4, 4, 8), 256, GEMM_SMEM>>>(
        wo1h, wo1l, 512, eh, el, 512, nullptr, nullptr, EWth, EWtl, nullptr,
        lens, 2, 512, 256, 2, 0, Ss * Hh, Hh * Ss);
    // K3: energies + softmax -> attn weights bf16 hi/lo
    attn_kernel<<<dim3(Tt / 16, Bb), 512, SMEM_ATTN>>>(v, lens);
    // K5: out[b] = tanh(attnw[b] @ EWt[b]^T + QW), K clamped to ceil32(len)
    gemm_mma_epi<<<dim3(8, 2, 8), 256, GEMM_SMEM>>>(
        awh, awl, 256, EWth, EWtl, 256, out, nullptr, nullptr, nullptr, QW,
        lens, 3, 256, 512, 3, Tt * Ss, Hh * Ss, Tt * Hh);
}

// round 13
// speedup vs baseline: 2.5190x; 1.1401x over previous
#include <cuda_runtime.h>
#include <cuda_bf16.h>
#include <math.h>
#include <stdint.h>

#define Bb 8
#define Tt 256
#define Ss 256
#define Hh 512
#define BT (Bb*Tt)

// ------------------------- scratch (device globals) -------------------------
__device__ float g_TA[BT * Hh];       // exp(2 * query @ W_s^T)
__device__ float g_TB[Bb * Ss * Hh];  // exp(2 * enc   @ W_h^T)
__device__ float g_QW[BT * Hh];       // query @ Wo2^T

__device__ __nv_bfloat16 g_qh[BT * Hh],    g_ql[BT * Hh];
__device__ __nv_bfloat16 g_eh[Bb*Ss*Hh],   g_el[Bb*Ss*Hh];
__device__ __nv_bfloat16 g_wcath[1024*Hh], g_wcatl[1024*Hh];  // [W_s ; Wo2]
__device__ __nv_bfloat16 g_whh[Hh*Hh],     g_whl[Hh*Hh];
__device__ __nv_bfloat16 g_wo1h[Hh*Hh],    g_wo1l[Hh*Hh];     // Wo1 compact
__device__ __nv_bfloat16 g_awh[BT * Ss],   g_awl[BT * Ss];    // attn weights
__device__ __nv_bfloat16 g_EWth[Bb*Hh*Ss], g_EWtl[Bb*Hh*Ss];  // (enc@Wo1^T)^T

// ------------------------- helpers -------------------------
__device__ __forceinline__ uint32_t smem_u32(const void* p) {
    uint32_t a;
    asm("{ .reg .u64 t; cvta.to.shared.u64 t, %1; cvt.u32.u64 %0, t; }" : "=r"(a) : "l"(p));
    return a;
}

#define LDSM4(r, addr) \
    asm volatile("ldmatrix.sync.aligned.m8n8.x4.shared.b16 {%0,%1,%2,%3}, [%4];" \
        : "=r"((r)[0]), "=r"((r)[1]), "=r"((r)[2]), "=r"((r)[3]) : "r"(addr))

#define MMA16816(c, a, b) \
    asm volatile("mma.sync.aligned.m16n8k16.row.col.f32.bf16.bf16.f32 " \
        "{%0,%1,%2,%3}, {%4,%5,%6,%7}, {%8,%9}, {%0,%1,%2,%3};" \
        : "+f"((c)[0]), "+f"((c)[1]), "+f"((c)[2]), "+f"((c)[3]) \
        : "r"((a)[0]), "r"((a)[1]), "r"((a)[2]), "r"((a)[3]), "r"((b)[0]), "r"((b)[1]))

#define CP16(dst, src) \
    asm volatile("cp.async.cg.shared.global [%0], [%1], 16;" :: "r"(dst), "l"(src))
#define CP_COMMIT() asm volatile("cp.async.commit_group;")

#define RCPF(r, x) asm("rcp.approx.f32 %0, %1;" : "=f"(r) : "f"(x))

__device__ __forceinline__ void hilo_pack(float4 x, uint2& ho, uint2& lo)
{
    __nv_bfloat16 h0 = __float2bfloat16(x.x), h1 = __float2bfloat16(x.y);
    __nv_bfloat16 h2 = __float2bfloat16(x.z), h3 = __float2bfloat16(x.w);
    __nv_bfloat16 l0 = __float2bfloat16(x.x - __bfloat162float(h0));
    __nv_bfloat16 l1 = __float2bfloat16(x.y - __bfloat162float(h1));
    __nv_bfloat16 l2 = __float2bfloat16(x.z - __bfloat162float(h2));
    __nv_bfloat16 l3 = __float2bfloat16(x.w - __bfloat162float(h3));
    __nv_bfloat162 hp0 = __halves2bfloat162(h0, h1), hp1 = __halves2bfloat162(h2, h3);
    __nv_bfloat162 lp0 = __halves2bfloat162(l0, l1), lp1 = __halves2bfloat162(l2, l3);
    ho.x = *reinterpret_cast<uint32_t*>(&hp0); ho.y = *reinterpret_cast<uint32_t*>(&hp1);
    lo.x = *reinterpret_cast<uint32_t*>(&lp0); lo.y = *reinterpret_cast<uint32_t*>(&lp1);
}

__device__ __forceinline__ void cvt4(const float* __restrict__ x,
                                     __nv_bfloat16* __restrict__ hi,
                                     __nv_bfloat16* __restrict__ lo, int i)
{
    float4 v = reinterpret_cast<const float4*>(x)[i];
    uint2 ho, loo;
    hilo_pack(v, ho, loo);
    reinterpret_cast<uint2*>(hi)[i] = ho;
    reinterpret_cast<uint2*>(lo)[i] = loo;
}

#define N4_Q  (BT*Hh/4)
#define N4_E  (Bb*Ss*Hh/4)
#define N4_WS (Hh*Hh/4)
#define N4_WO (Hh*2*Hh/4)
__global__ __launch_bounds__(256) void cvt_all(
    const float* q, const float* e, const float* ws, const float* wh, const float* wo)
{
    int i = blockIdx.x * blockDim.x + threadIdx.x;
    if (i < N4_Q)  { cvt4(q,  g_qh,  g_ql,  i); return; }  i -= N4_Q;
    if (i < N4_E)  { cvt4(e,  g_eh,  g_el,  i); return; }  i -= N4_E;
    if (i < N4_WS) { cvt4(ws, g_wcath, g_wcatl, i); return; }  i -= N4_WS;
    if (i < N4_WS) { cvt4(wh, g_whh, g_whl, i); return; }  i -= N4_WS;
    if (i < N4_WO) {
        int r = i >> 8, c4 = i & 255;
        float4 v = reinterpret_cast<const float4*>(wo)[i];
        uint2 ho, lo;
        hilo_pack(v, ho, lo);
        if (c4 < 128) {
            int di = r * 128 + c4;
            reinterpret_cast<uint2*>(g_wo1h)[di] = ho;
            reinterpret_cast<uint2*>(g_wo1l)[di] = lo;
        } else {
            int di = (512 + r) * 128 + (c4 - 128);
            reinterpret_cast<uint2*>(g_wcath)[di] = ho;
            reinterpret_cast<uint2*>(g_wcatl)[di] = lo;
        }
    }
}

// ---------------------------------------------------------------------------
// HMMA bf16x3 GEMM body (shared by stage1 + K5 kernels).
// modes: 1 exp(2x)->C ; 2 bf16 hi/lo -> Chi,Clo ; 3 tanh(x+QW)->C ;
//        5 split: n0<512 exp->C else linear->C2 (col-512)
// ---------------------------------------------------------------------------
#define OFF_AH 0
#define OFF_AL 10240
#define OFF_BH 20480
#define OFF_BL 25600
#define STG    30720
#define GEMM_SMEM (2*STG)

__device__ __noinline__ void gemm_body(
    const __nv_bfloat16* __restrict__ Ah, const __nv_bfloat16* __restrict__ Al,
    int astride,
    const __nv_bfloat16* __restrict__ Wh, const __nv_bfloat16* __restrict__ Wl,
    int wstride,
    float* __restrict__ C, float* __restrict__ C2,
    __nv_bfloat16* __restrict__ Chi, __nv_bfloat16* __restrict__ Clo,
    const float* __restrict__ QW,
    int NC, int Nout, int mode, size_t cofs, int m0, int n0)
{
    extern __shared__ char smem[];
    const uint32_t sb = smem_u32(smem);

    const int tid = threadIdx.x;
    const int wid = tid >> 5, lane = tid & 31;
    const int wm = (wid & 3) * 32;
    const int wn = (wid >> 2) * 32;

    const int ar = tid >> 2;
    const int ac = (tid & 3) * 8;
    const int g  = lane >> 3;
    const int rr = lane & 7;

    float acc[2][4][4];
    #pragma unroll
    for (int mi = 0; mi < 2; mi++)
        #pragma unroll
        for (int ni = 0; ni < 4; ni++)
            #pragma unroll
            for (int r = 0; r < 4; r++) acc[mi][ni][r] = 0.0f;

    auto load_stage = [&](int kc, int stg) {
        const int k0 = kc * 32;
        const uint32_t base = sb + stg * STG;
        #pragma unroll
        for (int r = 0; r < 2; r++) {
            int row = ar + r * 64;
            size_t gidx = (size_t)(m0 + row) * astride + k0 + ac;
            CP16(base + OFF_AH + row * 80 + ac * 2, &Ah[gidx]);
            CP16(base + OFF_AL + row * 80 + ac * 2, &Al[gidx]);
        }
        size_t gw = (size_t)(n0 + ar) * wstride + k0 + ac;
        CP16(base + OFF_BH + ar * 80 + ac * 2, &Wh[gw]);
        CP16(base + OFF_BL + ar * 80 + ac * 2, &Wl[gw]);
    };

    auto compute = [&](int stg) {
        const uint32_t base = sb + stg * STG;
        #pragma unroll
        for (int ks = 0; ks < 32; ks += 16) {
            uint32_t ah[2][4], al[2][4], bh[4][2], bl[4][2];
            const int colb = (ks + (g >> 1) * 8) * 2;
            #pragma unroll
            for (int mi = 0; mi < 2; mi++) {
                int row = wm + mi * 16 + (g & 1) * 8 + rr;
                LDSM4(ah[mi], base + OFF_AH + row * 80 + colb);
                LDSM4(al[mi], base + OFF_AL + row * 80 + colb);
            }
            #pragma unroll
            for (int nb = 0; nb < 2; nb++) {
                int row = wn + nb * 16 + (g & 1) * 8 + rr;
                uint32_t t[4];
                LDSM4(t, base + OFF_BH + row * 80 + colb);
                bh[nb*2+0][0] = t[0]; bh[nb*2+0][1] = t[2];
                bh[nb*2+1][0] = t[1]; bh[nb*2+1][1] = t[3];
                LDSM4(t, base + OFF_BL + row * 80 + colb);
                bl[nb*2+0][0] = t[0]; bl[nb*2+0][1] = t[2];
                bl[nb*2+1][0] = t[1]; bl[nb*2+1][1] = t[3];
            }
            #pragma unroll
            for (int mi = 0; mi < 2; mi++)
                #pragma unroll
                for (int ni = 0; ni < 4; ni++) {
                    MMA16816(acc[mi][ni], ah[mi], bh[ni]);
                    MMA16816(acc[mi][ni], ah[mi], bl[ni]);
                    MMA16816(acc[mi][ni], al[mi], bh[ni]);
                }
        }
    };

    load_stage(0, 0);
    CP_COMMIT();
    for (int kc = 0; kc < NC; kc++) {
        if (kc + 1 < NC) {
            load_stage(kc + 1, (kc + 1) & 1);
            CP_COMMIT();
            asm volatile("cp.async.wait_group 1;");
        } else {
            asm volatile("cp.async.wait_group 0;");
        }
        __syncthreads();
        compute(kc & 1);
        __syncthreads();
    }

    #pragma unroll
    for (int mi = 0; mi < 2; mi++)
        #pragma unroll
        for (int ni = 0; ni < 4; ni++) {
            int row = m0 + wm + mi * 16 + (lane >> 2);
            int col = n0 + wn + ni * 8 + (lane & 3) * 2;
            float x0 = acc[mi][ni][0], x1 = acc[mi][ni][1];
            float x2 = acc[mi][ni][2], x3 = acc[mi][ni][3];
            if (mode == 1 || (mode == 5 && n0 < 512)) {
                float2 v0 = { __expf(2.0f * x0), __expf(2.0f * x1) };
                float2 v1 = { __expf(2.0f * x2), __expf(2.0f * x3) };
                *reinterpret_cast<float2*>(&C[cofs + (size_t)row * Nout + col]) = v0;
                *reinterpret_cast<float2*>(&C[cofs + (size_t)(row + 8) * Nout + col]) = v1;
            } else if (mode == 5) {
                int cq = col - 512;
                float2 v0 = { x0, x1 };
                float2 v1 = { x2, x3 };
                *reinterpret_cast<float2*>(&C2[(size_t)row * Nout + cq]) = v0;
                *reinterpret_cast<float2*>(&C2[(size_t)(row + 8) * Nout + cq]) = v1;
            } else if (mode == 2) {
                __nv_bfloat16 h0 = __float2bfloat16(x0), h1 = __float2bfloat16(x1);
                __nv_bfloat16 h2 = __float2bfloat16(x2), h3 = __float2bfloat16(x3);
                __nv_bfloat16 l0 = __float2bfloat16(x0 - __bfloat162float(h0));
                __nv_bfloat16 l1 = __float2bfloat16(x1 - __bfloat162float(h1));
                __nv_bfloat16 l2 = __float2bfloat16(x2 - __bfloat162float(h2));
                __nv_bfloat16 l3 = __float2bfloat16(x3 - __bfloat162float(h3));
                __nv_bfloat162 hp0 = __halves2bfloat162(h0, h1), hp1 = __halves2bfloat162(h2, h3);
                __nv_bfloat162 lp0 = __halves2bfloat162(l0, l1), lp1 = __halves2bfloat162(l2, l3);
                *reinterpret_cast<uint32_t*>(&Chi[cofs + (size_t)row * Nout + col]) = *reinterpret_cast<uint32_t*>(&hp0);
                *reinterpret_cast<uint32_t*>(&Chi[cofs + (size_t)(row + 8) * Nout + col]) = *reinterpret_cast<uint32_t*>(&hp1);
                *reinterpret_cast<uint32_t*>(&Clo[cofs + (size_t)row * Nout + col]) = *reinterpret_cast<uint32_t*>(&lp0);
                *reinterpret_cast<uint32_t*>(&Clo[cofs + (size_t)(row + 8) * Nout + col]) = *reinterpret_cast<uint32_t*>(&lp1);
            } else if (mode == 3) {
                float2 q0 = *reinterpret_cast<const float2*>(&QW[(size_t)row * Nout + col]);
                float2 q1 = *reinterpret_cast<const float2*>(&QW[(size_t)(row + 8) * Nout + col]);
                float2 v0 = { tanhf(x0 + q0.x), tanhf(x1 + q0.y) };
                float2 v1 = { tanhf(x2 + q1.x), tanhf(x3 + q1.y) };
                *reinterpret_cast<float2*>(&C[cofs + (size_t)row * Nout + col]) = v0;
                *reinterpret_cast<float2*>(&C[cofs + (size_t)(row + 8) * Nout + col]) = v1;
            }
        }
}

// ---------------------------------------------------------------------------
// Stage 1: fused G1 + K2 + K2b in one 512-block launch (all independent).
// ---------------------------------------------------------------------------
__global__ __launch_bounds__(256, 2) void stage1(const int* __restrict__ lens)
{
    const int bid = blockIdx.x;
    if (bid < 256) {
        int m0 = (bid >> 4) * 128, n0 = (bid & 15) * 64;
        gemm_body(g_qh, g_ql, 512, g_wcath, g_wcatl, 512,
                  g_TA, g_QW, nullptr, nullptr, nullptr,
                  16, 512, 5, 0, m0, n0);
    } else if (bid < 384) {
        int local = bid - 256;
        int n0 = (local & 7) * 64, m0 = (local >> 3) * 128;
        if ((m0 & 255) >= lens[m0 >> 8]) return;
        gemm_body(g_eh, g_el, 512, g_whh, g_whl, 512,
                  g_TB, nullptr, nullptr, nullptr, nullptr,
                  16, 512, 1, 0, m0, n0);
    } else {
        int local = bid - 384;
        int n0 = (local & 3) * 64, m0 = ((local >> 2) & 3) * 128;
        int bz = local >> 4;
        int L = (lens[bz] + 31) & ~31;
        if (n0 >= L) return;
        gemm_body(g_wo1h, g_wo1l, 512,
                  g_eh + (size_t)bz * Ss * Hh, g_el + (size_t)bz * Ss * Hh, 512,
                  nullptr, nullptr, g_EWth, g_EWtl, nullptr,
                  16, 256, 2, (size_t)bz * Hh * Ss, m0, n0);
    }
}

// ---------------------------------------------------------------------------
// K5: out[b] = tanh(attnw[b] @ EWt[b]^T + QW[b]), K clamped to ceil32(len[b]).
// ---------------------------------------------------------------------------
__global__ __launch_bounds__(256, 2) void k5_kernel(
    float* __restrict__ out, const int* __restrict__ lens)
{
    const int bz = blockIdx.z;
    int NC = (lens[bz] + 31) >> 5;
    if (NC > 8) NC = 8;
    const int m0 = blockIdx.y * 128, n0 = blockIdx.x * 64;
    gemm_body(g_awh + (size_t)bz * Tt * Ss, g_awl + (size_t)bz * Tt * Ss, 256,
              g_EWth + (size_t)bz * Hh * Ss, g_EWtl + (size_t)bz * Hh * Ss, 256,
              out + (size_t)bz * Tt * Hh, nullptr, nullptr, nullptr,
              g_QW + (size_t)bz * Tt * Hh,
              NC, 512, 3, 0, m0, n0);
}

// ---------------------------------------------------------------------------
// K3: energies + softmax -> attn weights (bf16 hi/lo), length-aware.
// ---------------------------------------------------------------------------
#define CPAD 68
#define BUFSZ (272 * CPAD)
#define SMEM_ATTN ((2*BUFSZ + 512 + 16*256) * 4)

__global__ __launch_bounds__(512) void attn_kernel(
    const float* __restrict__ v, const int* __restrict__ lens)
{
    extern __shared__ float sm[];
    float* buf = sm;
    float* vb  = sm + 2 * BUFSZ;
    float* en  = vb + 512;

    const uint32_t sb = smem_u32(sm);
    const int tid  = threadIdx.x;
    const int w    = tid >> 5;
    const int lane = tid & 31;
    const int stile = w & 7;
    const int tg    = w >> 3;
    const int b  = blockIdx.y;
    const int t0 = blockIdx.x * 16;
    const int len = lens[b];
    const int lenc = (len + 31) & ~31;

    if (tid < 128)
        *reinterpret_cast<float4*>(&vb[tid * 4]) =
            *reinterpret_cast<const float4*>(&v[tid * 4]);

    auto load_chunk = [&](int hc, int bb) {
        const uint32_t base = sb + bb * BUFSZ * 4;
        #pragma unroll
        for (int k = 0; k < 8; k++) {
            int idx = tid + k * 512;
            int row = idx >> 4, c4 = idx & 15;
            if (row < lenc)
                CP16(base + (row * CPAD + c4 * 4) * 4,
                     &g_TB[(size_t)(b * Ss + row) * Hh + hc * 64 + c4 * 4]);
        }
        if (tid < 256) {
            int row = tid >> 4, c4 = tid & 15;
            CP16(base + ((256 + row) * CPAD + c4 * 4) * 4,
                 &g_TA[(size_t)(b * Tt + t0 + row) * Hh + hc * 64 + c4 * 4]);
        }
    };

    float acc[8];
    #pragma unroll
    for (int j = 0; j < 8; j++) acc[j] = 0.0f;

    const bool active = (stile * 32) < len;

    load_chunk(0, 0);
    CP_COMMIT();
    for (int hc = 0; hc < 8; hc++) {
        if (hc + 1 < 8) {
            load_chunk(hc + 1, (hc + 1) & 1);
            CP_COMMIT();
            asm volatile("cp.async.wait_group 1;");
        } else {
            asm volatile("cp.async.wait_group 0;");
        }
        __syncthreads();

        if (active) {
            const float* eb = buf + (hc & 1) * BUFSZ;
            const float* qa = eb + 256 * CPAD;
            const float* erow = eb + (stile * 32 + lane) * CPAD;
            const float* vc = vb + hc * 64;
            const float* qg = qa + tg * 8 * CPAD;

            #pragma unroll 2
            for (int h4 = 0; h4 < 16; h4++) {
                float4 E = *reinterpret_cast<const float4*>(&erow[h4 * 4]);
                float4 V = *reinterpret_cast<const float4*>(&vc[h4 * 4]);
                #pragma unroll
                for (int j = 0; j < 8; j++) {
                    float4 A = *reinterpret_cast<const float4*>(&qg[j * CPAD + h4 * 4]);
                    float d0 = fmaf(A.x, E.x, 1.0f);
                    float d1 = fmaf(A.y, E.y, 1.0f);
                    float d2 = fmaf(A.z, E.z, 1.0f);
                    float d3 = fmaf(A.w, E.w, 1.0f);
                    float n01 = fmaf(V.y, d0, V.x * d1);
                    float n23 = fmaf(V.w, d2, V.z * d3);
                    float p01 = d0 * d1, p23 = d2 * d3;
                    float r01, r23;
                    RCPF(r01, p01); RCPF(r23, p23);
                    acc[j] = fmaf(n01, r01, acc[j]);
                    acc[j] = fmaf(n23, r23, acc[j]);
                }
            }
        }
        __syncthreads();
    }

    {
        int s = stile * 32 + lane;
        #pragma unroll
        for (int j = 0; j < 8; j++) {
            int t = tg * 8 + j;
            en[t * 256 + s] = (s < len) ? (-2.0f * acc[j]) : -INFINITY;
        }
    }
    __syncthreads();

    {
        float e[8];
        float m = -INFINITY;
        #pragma unroll
        for (int j = 0; j < 8; j++) {
            e[j] = en[w * 256 + lane + 32 * j];
            m = fmaxf(m, e[j]);
        }
        #pragma unroll
        for (int o = 16; o; o >>= 1) m = fmaxf(m, __shfl_xor_sync(0xffffffffu, m, o));
        float sum = 0.0f;
        #pragma unroll
        for (int j = 0; j < 8; j++) { e[j] = __expf(e[j] - m); sum += e[j]; }
        #pragma unroll
        for (int o = 16; o; o >>= 1) sum += __shfl_xor_sync(0xffffffffu, sum, o);
        float rs; RCPF(rs, sum);
        #pragma unroll
        for (int j = 0; j < 8; j++) en[w * 256 + lane + 32 * j] = e[j] * rs;
    }
    __syncthreads();

    #pragma unroll
    for (int k = 0; k < 2; k++) {
        int i = tid + k * 512;
        int row = i >> 6, c4 = i & 63;
        float4 x = *reinterpret_cast<const float4*>(&en[row * 256 + c4 * 4]);
        uint2 ho, lo;
        hilo_pack(x, ho, lo);
        size_t gidx = (size_t)(b * Tt + t0 + row) * Ss + c4 * 4;
        *reinterpret_cast<uint2*>(&g_awh[gidx]) = ho;
        *reinterpret_cast<uint2*>(&g_awl[gidx]) = lo;
    }
}

// ---------------------------------------------------------------------------
extern "C" void kernel_launch(void* const* d_in, const int* in_sizes, int n_in,
                              void* d_out, int out_size)
{
    const float* query = (const float*)d_in[0];
    const float* enc   = (const float*)d_in[1];
    const int*   lens  = (const int*)d_in[2];
    const float* W_s   = (const float*)d_in[3];
    const float* W_h   = (const float*)d_in[4];
    const float* v     = (const float*)d_in[5];
    const float* W_out = (const float*)d_in[6];
    float* out = (float*)d_out;

    cudaFuncSetAttribute(attn_kernel,
                         cudaFuncAttributeMaxDynamicSharedMemorySize, SMEM_ATTN);
    cudaFuncSetAttribute(stage1,
                         cudaFuncAttributeMaxDynamicSharedMemorySize, GEMM_SMEM);
    cudaFuncSetAttribute(k5_kernel,
                         cudaFuncAttributeMaxDynamicSharedMemorySize, GEMM_SMEM);

    const int TOT4 = N4_Q + N4_E + 2 * N4_WS + N4_WO;
    cvt_all<<<TOT4 / 256, 256>>>(query, enc, W_s, W_h, W_out);

    // Stage 1: G1 + K2 + K2b fused (512 blocks, 2 CTAs/SM co-resident)
    stage1<<<512, 256, GEMM_SMEM>>>(lens);
    // K3: energies + softmax -> attn weights bf16 hi/lo
    attn_kernel<<<dim3(Tt / 16, Bb), 512, SMEM_ATTN>>>(v, lens);
    // K5: out[b] = tanh(attnw[b] @ EWt[b]^T + QW[b])
    k5_kernel<<<dim3(8, 2, 8), 256, GEMM_SMEM>>>(out, lens);
}

// round 14
// speedup vs baseline: 2.5645x; 1.0181x over previous
#include <cuda_runtime.h>
#include <cuda_bf16.h>
#include <math.h>
#include <stdint.h>

#define Bb 8
#define Tt 256
#define Ss 256
#define Hh 512
#define BT (Bb*Tt)

// ------------------------- scratch (device globals) -------------------------
__device__ float g_TA[BT * Hh];       // exp(2 * query @ W_s^T)
__device__ float g_TB[Bb * Ss * Hh];  // exp(2 * enc   @ W_h^T)
__device__ float g_QW[BT * Hh];       // query @ Wo2^T

__device__ __nv_bfloat16 g_qh[BT * Hh],    g_ql[BT * Hh];
__device__ __nv_bfloat16 g_eh[Bb*Ss*Hh],   g_el[Bb*Ss*Hh];
__device__ __nv_bfloat16 g_wcath[1024*Hh], g_wcatl[1024*Hh];  // [W_s ; Wo2]
__device__ __nv_bfloat16 g_whh[Hh*Hh],     g_whl[Hh*Hh];
__device__ __nv_bfloat16 g_wo1h[Hh*Hh],    g_wo1l[Hh*Hh];     // Wo1 compact
__device__ __nv_bfloat16 g_awh[BT * Ss],   g_awl[BT * Ss];    // attn weights
__device__ __nv_bfloat16 g_EWth[Bb*Hh*Ss], g_EWtl[Bb*Hh*Ss];  // (enc@Wo1^T)^T

// ------------------------- helpers -------------------------
__device__ __forceinline__ uint32_t smem_u32(const void* p) {
    uint32_t a;
    asm("{ .reg .u64 t; cvta.to.shared.u64 t, %1; cvt.u32.u64 %0, t; }" : "=r"(a) : "l"(p));
    return a;
}

#define LDSM4(r, addr) \
    asm volatile("ldmatrix.sync.aligned.m8n8.x4.shared.b16 {%0,%1,%2,%3}, [%4];" \
        : "=r"((r)[0]), "=r"((r)[1]), "=r"((r)[2]), "=r"((r)[3]) : "r"(addr))

#define MMA16816(c, a, b) \
    asm volatile("mma.sync.aligned.m16n8k16.row.col.f32.bf16.bf16.f32 " \
        "{%0,%1,%2,%3}, {%4,%5,%6,%7}, {%8,%9}, {%0,%1,%2,%3};" \
        : "+f"((c)[0]), "+f"((c)[1]), "+f"((c)[2]), "+f"((c)[3]) \
        : "r"((a)[0]), "r"((a)[1]), "r"((a)[2]), "r"((a)[3]), "r"((b)[0]), "r"((b)[1]))

#define CP16(dst, src) \
    asm volatile("cp.async.cg.shared.global [%0], [%1], 16;" :: "r"(dst), "l"(src))
#define CP_COMMIT() asm volatile("cp.async.commit_group;")

#define RCPF(r, x) asm("rcp.approx.f32 %0, %1;" : "=f"(r) : "f"(x))

__device__ __forceinline__ void hilo_pack(float4 x, uint2& ho, uint2& lo)
{
    __nv_bfloat16 h0 = __float2bfloat16(x.x), h1 = __float2bfloat16(x.y);
    __nv_bfloat16 h2 = __float2bfloat16(x.z), h3 = __float2bfloat16(x.w);
    __nv_bfloat16 l0 = __float2bfloat16(x.x - __bfloat162float(h0));
    __nv_bfloat16 l1 = __float2bfloat16(x.y - __bfloat162float(h1));
    __nv_bfloat16 l2 = __float2bfloat16(x.z - __bfloat162float(h2));
    __nv_bfloat16 l3 = __float2bfloat16(x.w - __bfloat162float(h3));
    __nv_bfloat162 hp0 = __halves2bfloat162(h0, h1), hp1 = __halves2bfloat162(h2, h3);
    __nv_bfloat162 lp0 = __halves2bfloat162(l0, l1), lp1 = __halves2bfloat162(l2, l3);
    ho.x = *reinterpret_cast<uint32_t*>(&hp0); ho.y = *reinterpret_cast<uint32_t*>(&hp1);
    lo.x = *reinterpret_cast<uint32_t*>(&lp0); lo.y = *reinterpret_cast<uint32_t*>(&lp1);
}

__device__ __forceinline__ void cvt4(const float* __restrict__ x,
                                     __nv_bfloat16* __restrict__ hi,
                                     __nv_bfloat16* __restrict__ lo, int i)
{
    float4 v = reinterpret_cast<const float4*>(x)[i];
    uint2 ho, loo;
    hilo_pack(v, ho, loo);
    reinterpret_cast<uint2*>(hi)[i] = ho;
    reinterpret_cast<uint2*>(lo)[i] = loo;
}

#define N4_Q  (BT*Hh/4)
#define N4_E  (Bb*Ss*Hh/4)
#define N4_WS (Hh*Hh/4)
#define N4_WO (Hh*2*Hh/4)
__global__ __launch_bounds__(256) void cvt_all(
    const float* q, const float* e, const float* ws, const float* wh, const float* wo)
{
    int i = blockIdx.x * blockDim.x + threadIdx.x;
    if (i < N4_Q)  { cvt4(q,  g_qh,  g_ql,  i); return; }  i -= N4_Q;
    if (i < N4_E)  { cvt4(e,  g_eh,  g_el,  i); return; }  i -= N4_E;
    if (i < N4_WS) { cvt4(ws, g_wcath, g_wcatl, i); return; }  i -= N4_WS;
    if (i < N4_WS) { cvt4(wh, g_whh, g_whl, i); return; }  i -= N4_WS;
    if (i < N4_WO) {
        int r = i >> 8, c4 = i & 255;
        float4 v = reinterpret_cast<const float4*>(wo)[i];
        uint2 ho, lo;
        hilo_pack(v, ho, lo);
        if (c4 < 128) {
            int di = r * 128 + c4;
            reinterpret_cast<uint2*>(g_wo1h)[di] = ho;
            reinterpret_cast<uint2*>(g_wo1l)[di] = lo;
        } else {
            int di = (512 + r) * 128 + (c4 - 128);
            reinterpret_cast<uint2*>(g_wcath)[di] = ho;
            reinterpret_cast<uint2*>(g_wcatl)[di] = lo;
        }
    }
}

// ---------------------------------------------------------------------------
// HMMA bf16x3 GEMM body, STAGES-deep cp.async pipeline.
// modes: 1 exp(2x)->C ; 2 bf16 hi/lo -> Chi,Clo ; 3 tanh(x+QW)->C ;
//        5 split: n0<512 exp->C else linear->C2 (col-512)
// ---------------------------------------------------------------------------
#define OFF_AH 0
#define OFF_AL 10240
#define OFF_BH 20480
#define OFF_BL 25600
#define STG    30720
#define GEMM_SMEM2 (2*STG)
#define GEMM_SMEM3 (3*STG)

template<int STAGES>
__device__ __noinline__ void gemm_body(
    const __nv_bfloat16* __restrict__ Ah, const __nv_bfloat16* __restrict__ Al,
    int astride,
    const __nv_bfloat16* __restrict__ Wh, const __nv_bfloat16* __restrict__ Wl,
    int wstride,
    float* __restrict__ C, float* __restrict__ C2,
    __nv_bfloat16* __restrict__ Chi, __nv_bfloat16* __restrict__ Clo,
    const float* __restrict__ QW,
    int NC, int Nout, int mode, size_t cofs, int m0, int n0)
{
    extern __shared__ char smem[];
    const uint32_t sb = smem_u32(smem);

    const int tid = threadIdx.x;
    const int wid = tid >> 5, lane = tid & 31;
    const int wm = (wid & 3) * 32;
    const int wn = (wid >> 2) * 32;

    const int ar = tid >> 2;
    const int ac = (tid & 3) * 8;
    const int g  = lane >> 3;
    const int rr = lane & 7;

    float acc[2][4][4];
    #pragma unroll
    for (int mi = 0; mi < 2; mi++)
        #pragma unroll
        for (int ni = 0; ni < 4; ni++)
            #pragma unroll
            for (int r = 0; r < 4; r++) acc[mi][ni][r] = 0.0f;

    auto load_stage = [&](int kc, int stg) {
        const int k0 = kc * 32;
        const uint32_t base = sb + stg * STG;
        #pragma unroll
        for (int r = 0; r < 2; r++) {
            int row = ar + r * 64;
            size_t gidx = (size_t)(m0 + row) * astride + k0 + ac;
            CP16(base + OFF_AH + row * 80 + ac * 2, &Ah[gidx]);
            CP16(base + OFF_AL + row * 80 + ac * 2, &Al[gidx]);
        }
        size_t gw = (size_t)(n0 + ar) * wstride + k0 + ac;
        CP16(base + OFF_BH + ar * 80 + ac * 2, &Wh[gw]);
        CP16(base + OFF_BL + ar * 80 + ac * 2, &Wl[gw]);
    };

    auto compute = [&](int stg) {
        const uint32_t base = sb + stg * STG;
        #pragma unroll
        for (int ks = 0; ks < 32; ks += 16) {
            uint32_t ah[2][4], al[2][4], bh[4][2], bl[4][2];
            const int colb = (ks + (g >> 1) * 8) * 2;
            #pragma unroll
            for (int mi = 0; mi < 2; mi++) {
                int row = wm + mi * 16 + (g & 1) * 8 + rr;
                LDSM4(ah[mi], base + OFF_AH + row * 80 + colb);
                LDSM4(al[mi], base + OFF_AL + row * 80 + colb);
            }
            #pragma unroll
            for (int nb = 0; nb < 2; nb++) {
                int row = wn + nb * 16 + (g & 1) * 8 + rr;
                uint32_t t[4];
                LDSM4(t, base + OFF_BH + row * 80 + colb);
                bh[nb*2+0][0] = t[0]; bh[nb*2+0][1] = t[2];
                bh[nb*2+1][0] = t[1]; bh[nb*2+1][1] = t[3];
                LDSM4(t, base + OFF_BL + row * 80 + colb);
                bl[nb*2+0][0] = t[0]; bl[nb*2+0][1] = t[2];
                bl[nb*2+1][0] = t[1]; bl[nb*2+1][1] = t[3];
            }
            #pragma unroll
            for (int mi = 0; mi < 2; mi++)
                #pragma unroll
                for (int ni = 0; ni < 4; ni++) {
                    MMA16816(acc[mi][ni], ah[mi], bh[ni]);
                    MMA16816(acc[mi][ni], ah[mi], bl[ni]);
                    MMA16816(acc[mi][ni], al[mi], bh[ni]);
                }
        }
    };

    load_stage(0, 0);
    CP_COMMIT();
    if (STAGES == 3 && NC > 1) { load_stage(1, 1); CP_COMMIT(); }
    for (int kc = 0; kc < NC; kc++) {
        if (STAGES == 2) {
            if (kc + 1 < NC) {
                load_stage(kc + 1, (kc + 1) & 1);
                CP_COMMIT();
                asm volatile("cp.async.wait_group 1;");
            } else {
                asm volatile("cp.async.wait_group 0;");
            }
        } else {
            if (kc + 2 < NC) {
                load_stage(kc + 2, (kc + 2) % 3);
                CP_COMMIT();
                asm volatile("cp.async.wait_group 2;");
            } else if (kc + 1 < NC) {
                asm volatile("cp.async.wait_group 1;");
            } else {
                asm volatile("cp.async.wait_group 0;");
            }
        }
        __syncthreads();
        compute(kc % STAGES);
        __syncthreads();
    }

    #pragma unroll
    for (int mi = 0; mi < 2; mi++)
        #pragma unroll
        for (int ni = 0; ni < 4; ni++) {
            int row = m0 + wm + mi * 16 + (lane >> 2);
            int col = n0 + wn + ni * 8 + (lane & 3) * 2;
            float x0 = acc[mi][ni][0], x1 = acc[mi][ni][1];
            float x2 = acc[mi][ni][2], x3 = acc[mi][ni][3];
            if (mode == 1 || (mode == 5 && n0 < 512)) {
                float2 v0 = { __expf(2.0f * x0), __expf(2.0f * x1) };
                float2 v1 = { __expf(2.0f * x2), __expf(2.0f * x3) };
                *reinterpret_cast<float2*>(&C[cofs + (size_t)row * Nout + col]) = v0;
                *reinterpret_cast<float2*>(&C[cofs + (size_t)(row + 8) * Nout + col]) = v1;
            } else if (mode == 5) {
                int cq = col - 512;
                float2 v0 = { x0, x1 };
                float2 v1 = { x2, x3 };
                *reinterpret_cast<float2*>(&C2[(size_t)row * Nout + cq]) = v0;
                *reinterpret_cast<float2*>(&C2[(size_t)(row + 8) * Nout + cq]) = v1;
            } else if (mode == 2) {
                __nv_bfloat16 h0 = __float2bfloat16(x0), h1 = __float2bfloat16(x1);
                __nv_bfloat16 h2 = __float2bfloat16(x2), h3 = __float2bfloat16(x3);
                __nv_bfloat16 l0 = __float2bfloat16(x0 - __bfloat162float(h0));
                __nv_bfloat16 l1 = __float2bfloat16(x1 - __bfloat162float(h1));
                __nv_bfloat16 l2 = __float2bfloat16(x2 - __bfloat162float(h2));
                __nv_bfloat16 l3 = __float2bfloat16(x3 - __bfloat162float(h3));
                __nv_bfloat162 hp0 = __halves2bfloat162(h0, h1), hp1 = __halves2bfloat162(h2, h3);
                __nv_bfloat162 lp0 = __halves2bfloat162(l0, l1), lp1 = __halves2bfloat162(l2, l3);
                *reinterpret_cast<uint32_t*>(&Chi[cofs + (size_t)row * Nout + col]) = *reinterpret_cast<uint32_t*>(&hp0);
                *reinterpret_cast<uint32_t*>(&Chi[cofs + (size_t)(row + 8) * Nout + col]) = *reinterpret_cast<uint32_t*>(&hp1);
                *reinterpret_cast<uint32_t*>(&Clo[cofs + (size_t)row * Nout + col]) = *reinterpret_cast<uint32_t*>(&lp0);
                *reinterpret_cast<uint32_t*>(&Clo[cofs + (size_t)(row + 8) * Nout + col]) = *reinterpret_cast<uint32_t*>(&lp1);
            } else if (mode == 3) {
                float2 q0 = *reinterpret_cast<const float2*>(&QW[(size_t)row * Nout + col]);
                float2 q1 = *reinterpret_cast<const float2*>(&QW[(size_t)(row + 8) * Nout + col]);
                float2 v0 = { tanhf(x0 + q0.x), tanhf(x1 + q0.y) };
                float2 v1 = { tanhf(x2 + q1.x), tanhf(x3 + q1.y) };
                *reinterpret_cast<float2*>(&C[cofs + (size_t)row * Nout + col]) = v0;
                *reinterpret_cast<float2*>(&C[cofs + (size_t)(row + 8) * Nout + col]) = v1;
            }
        }
}

// ---------------------------------------------------------------------------
// Stage 1: fused G1 + K2 + K2b, 512 blocks, 3 CTAs/SM co-resident.
// ---------------------------------------------------------------------------
__global__ __launch_bounds__(256, 3) void stage1(const int* __restrict__ lens)
{
    const int bid = blockIdx.x;
    if (bid < 256) {
        int m0 = (bid >> 4) * 128, n0 = (bid & 15) * 64;
        gemm_body<2>(g_qh, g_ql, 512, g_wcath, g_wcatl, 512,
                     g_TA, g_QW, nullptr, nullptr, nullptr,
                     16, 512, 5, 0, m0, n0);
    } else if (bid < 384) {
        int local = bid - 256;
        int n0 = (local & 7) * 64, m0 = (local >> 3) * 128;
        if ((m0 & 255) >= lens[m0 >> 8]) return;
        gemm_body<2>(g_eh, g_el, 512, g_whh, g_whl, 512,
                     g_TB, nullptr, nullptr, nullptr, nullptr,
                     16, 512, 1, 0, m0, n0);
    } else {
        int local = bid - 384;
        int n0 = (local & 3) * 64, m0 = ((local >> 2) & 3) * 128;
        int bz = local >> 4;
        int L = (lens[bz] + 31) & ~31;
        if (n0 >= L) return;
        gemm_body<2>(g_wo1h, g_wo1l, 512,
                     g_eh + (size_t)bz * Ss * Hh, g_el + (size_t)bz * Ss * Hh, 512,
                     nullptr, nullptr, g_EWth, g_EWtl, nullptr,
                     16, 256, 2, (size_t)bz * Hh * Ss, m0, n0);
    }
}

// ---------------------------------------------------------------------------
// K5: out[b] = tanh(attnw[b] @ EWt[b]^T + QW[b]), 3-stage pipeline.
// ---------------------------------------------------------------------------
__global__ __launch_bounds__(256) void k5_kernel(
    float* __restrict__ out, const int* __restrict__ lens)
{
    const int bz = blockIdx.z;
    int NC = (lens[bz] + 31) >> 5;
    if (NC > 8) NC = 8;
    const int m0 = blockIdx.y * 128, n0 = blockIdx.x * 64;
    gemm_body<3>(g_awh + (size_t)bz * Tt * Ss, g_awl + (size_t)bz * Tt * Ss, 256,
                 g_EWth + (size_t)bz * Hh * Ss, g_EWtl + (size_t)bz * Hh * Ss, 256,
                 out + (size_t)bz * Tt * Hh, nullptr, nullptr, nullptr,
                 g_QW + (size_t)bz * Tt * Hh,
                 NC, 512, 3, 0, m0, n0);
}

// ---------------------------------------------------------------------------
// K3: energies + softmax -> attn weights (bf16 hi/lo).
// 1024 threads (8 warps/SMSP). h split in 2 halves across warp sets; two
// parallel 32-h chunk streams, double-buffered (4 buffers). Partial energies
// in en0/en1, combined + masked at softmax read.
// Warp w: hh = w>>4, wl = w&15, tg = wl>>3 (8 t), stile = wl&7 (lane = s).
// ---------------------------------------------------------------------------
#define BUF1F (272 * 36)                       // floats per buffer (E 256 rows + qa 16)
#define SMEM_ATTN ((4*BUF1F + 512 + 2*4096) * 4)

__global__ __launch_bounds__(1024) void attn_kernel(
    const float* __restrict__ v, const int* __restrict__ lens)
{
    extern __shared__ float sm[];
    float* vb  = sm + 4 * BUF1F;     // 512
    float* en0 = vb + 512;           // 16 x 256 (half 0 partials)
    float* en1 = en0 + 4096;         // 16 x 256 (half 1 partials)

    const uint32_t sb = smem_u32(sm);
    const int tid  = threadIdx.x;
    const int w    = tid >> 5;
    const int lane = tid & 31;
    const int hh    = w >> 4;        // h-half 0/1
    const int wl    = w & 15;
    const int tg    = wl >> 3;       // t-group (8 t each)
    const int stile = wl & 7;        // s-tile of 32
    const int b  = blockIdx.y;
    const int t0 = blockIdx.x * 16;
    const int len = lens[b];
    const int lenc = (len + 31) & ~31;

    if (tid < 128)
        *reinterpret_cast<float4*>(&vb[tid * 4]) =
            *reinterpret_cast<const float4*>(&v[tid * 4]);

    // load 32-h chunk pair (i, 8+i) into buffers (0,par),(1,par)
    auto load_pair = [&](int i, int par) {
        #pragma unroll
        for (int half = 0; half < 2; half++) {
            const int chunk = half * 8 + i;
            const uint32_t base = sb + (half * 2 + par) * (BUF1F * 4);
            #pragma unroll
            for (int k = 0; k < 2; k++) {          // E: 256 rows x 8 float4
                int idx = tid + k * 1024;
                int row = idx >> 3, c4 = idx & 7;
                if (row < lenc)
                    CP16(base + (row * 36 + c4 * 4) * 4,
                         &g_TB[(size_t)(b * Ss + row) * Hh + chunk * 32 + c4 * 4]);
            }
            if (tid < 128) {                        // qa: 16 rows x 8 float4
                int row = tid >> 3, c4 = tid & 7;
                CP16(base + ((256 + row) * 36 + c4 * 4) * 4,
                     &g_TA[(size_t)(b * Tt + t0 + row) * Hh + chunk * 32 + c4 * 4]);
            }
        }
    };

    float acc[8];
    #pragma unroll
    for (int j = 0; j < 8; j++) acc[j] = 0.0f;

    const bool active = (stile * 32) < len;

    load_pair(0, 0);
    CP_COMMIT();
    for (int i = 0; i < 8; i++) {
        if (i + 1 < 8) {
            load_pair(i + 1, (i + 1) & 1);
            CP_COMMIT();
            asm volatile("cp.async.wait_group 1;");
        } else {
            asm volatile("cp.async.wait_group 0;");
        }
        __syncthreads();

        if (active) {
            const float* bufp = sm + (hh * 2 + (i & 1)) * BUF1F;
            const float* erow = bufp + (stile * 32 + lane) * 36;
            const float* qg   = bufp + (256 + tg * 8) * 36;
            const float* vc   = vb + hh * 256 + i * 32;

            #pragma unroll 2
            for (int h4 = 0; h4 < 8; h4++) {
                float4 E = *reinterpret_cast<const float4*>(&erow[h4 * 4]);
                float4 V = *reinterpret_cast<const float4*>(&vc[h4 * 4]);
                #pragma unroll
                for (int j = 0; j < 8; j++) {
                    float4 A = *reinterpret_cast<const float4*>(&qg[j * 36 + h4 * 4]);
                    float d0 = fmaf(A.x, E.x, 1.0f);
                    float d1 = fmaf(A.y, E.y, 1.0f);
                    float d2 = fmaf(A.z, E.z, 1.0f);
                    float d3 = fmaf(A.w, E.w, 1.0f);
                    float n01 = fmaf(V.y, d0, V.x * d1);
                    float n23 = fmaf(V.w, d2, V.z * d3);
                    float p01 = d0 * d1, p23 = d2 * d3;
                    float r01, r23;
                    RCPF(r01, p01); RCPF(r23, p23);
                    acc[j] = fmaf(n01, r01, acc[j]);
                    acc[j] = fmaf(n23, r23, acc[j]);
                }
            }
        }
        __syncthreads();
    }

    // write partials (only active warps; masked entries read-guarded below)
    if (active) {
        float* enp = hh ? en1 : en0;
        int s = stile * 32 + lane;
        #pragma unroll
        for (int j = 0; j < 8; j++)
            enp[(tg * 8 + j) * 256 + s] = acc[j];
    }
    __syncthreads();

    // softmax: warp w<16 handles row t=w; combine halves + mask at read
    if (w < 16) {
        float e[8];
        float m = -INFINITY;
        #pragma unroll
        for (int j = 0; j < 8; j++) {
            int s = lane + 32 * j;
            int idx = w * 256 + s;
            e[j] = (s < len) ? (-2.0f * (en0[idx] + en1[idx])) : -INFINITY;
            m = fmaxf(m, e[j]);
        }
        #pragma unroll
        for (int o = 16; o; o >>= 1) m = fmaxf(m, __shfl_xor_sync(0xffffffffu, m, o));
        float sum = 0.0f;
        #pragma unroll
        for (int j = 0; j < 8; j++) { e[j] = __expf(e[j] - m); sum += e[j]; }
        #pragma unroll
        for (int o = 16; o; o >>= 1) sum += __shfl_xor_sync(0xffffffffu, sum, o);
        float rs; RCPF(rs, sum);
        #pragma unroll
        for (int j = 0; j < 8; j++) en0[w * 256 + lane + 32 * j] = e[j] * rs;
    }
    __syncthreads();

    // emit weights as bf16 hi/lo: 4096 f32 = 1024 float4, one per thread
    {
        int row = tid >> 6, c4 = tid & 63;
        float4 x = *reinterpret_cast<const float4*>(&en0[row * 256 + c4 * 4]);
        uint2 ho, lo;
        hilo_pack(x, ho, lo);
        size_t gidx = (size_t)(b * Tt + t0 + row) * Ss + c4 * 4;
        *reinterpret_cast<uint2*>(&g_awh[gidx]) = ho;
        *reinterpret_cast<uint2*>(&g_awl[gidx]) = lo;
    }
}

// ---------------------------------------------------------------------------
extern "C" void kernel_launch(void* const* d_in, const int* in_sizes, int n_in,
                              void* d_out, int out_size)
{
    const float* query = (const float*)d_in[0];
    const float* enc   = (const float*)d_in[1];
    const int*   lens  = (const int*)d_in[2];
    const float* W_s   = (const float*)d_in[3];
    const float* W_h   = (const float*)d_in[4];
    const float* v     = (const float*)d_in[5];
    const float* W_out = (const float*)d_in[6];
    float* out = (float*)d_out;

    cudaFuncSetAttribute(attn_kernel,
                         cudaFuncAttributeMaxDynamicSharedMemorySize, SMEM_ATTN);
    cudaFuncSetAttribute(stage1,
                         cudaFuncAttributeMaxDynamicSharedMemorySize, GEMM_SMEM2);
    cudaFuncSetAttribute(k5_kernel,
                         cudaFuncAttributeMaxDynamicSharedMemorySize, GEMM_SMEM3);

    const int TOT4 = N4_Q + N4_E + 2 * N4_WS + N4_WO;
    cvt_all<<<TOT4 / 256, 256>>>(query, enc, W_s, W_h, W_out);

    // Stage 1: G1 + K2 + K2b fused (512 blocks, 3 CTAs/SM co-resident)
    stage1<<<512, 256, GEMM_SMEM2>>>(lens);
    // K3: energies + softmax -> attn weights bf16 hi/lo (1024 threads)
    attn_kernel<<<dim3(Tt / 16, Bb), 1024, SMEM_ATTN>>>(v, lens);
    // K5: out[b] = tanh(attnw[b] @ EWt[b]^T + QW[b]), 3-stage pipeline
    k5_kernel<<<dim3(8, 2, 8), 256, GEMM_SMEM3>>>(out, lens);
}

// round 16
// speedup vs baseline: 2.6770x; 1.0439x over previous
#include <cuda_runtime.h>
#include <cuda_bf16.h>
#include <math.h>
#include <stdint.h>

#define Bb 8
#define Tt 256
#define Ss 256
#define Hh 512
#define BT (Bb*Tt)

// ------------------------- scratch (device globals) -------------------------
__device__ float g_TA[BT * Hh];       // exp(2 * query @ W_s^T)
__device__ float g_TB[Bb * Ss * Hh];  // exp(2 * enc   @ W_h^T)
__device__ float g_QW[BT * Hh];       // query @ Wo2^T

__device__ __nv_bfloat16 g_qh[BT * Hh],    g_ql[BT * Hh];
__device__ __nv_bfloat16 g_eh[Bb*Ss*Hh],   g_el[Bb*Ss*Hh];
__device__ __nv_bfloat16 g_wcath[1024*Hh], g_wcatl[1024*Hh];  // [W_s ; Wo2]
__device__ __nv_bfloat16 g_whh[Hh*Hh],     g_whl[Hh*Hh];
__device__ __nv_bfloat16 g_wo1h[Hh*Hh],    g_wo1l[Hh*Hh];     // Wo1 compact
__device__ __nv_bfloat16 g_awh[BT * Ss],   g_awl[BT * Ss];    // attn weights
__device__ __nv_bfloat16 g_EWth[Bb*Hh*Ss], g_EWtl[Bb*Hh*Ss];  // (enc@Wo1^T)^T

// ------------------------- helpers -------------------------
__device__ __forceinline__ uint32_t smem_u32(const void* p) {
    uint32_t a;
    asm("{ .reg .u64 t; cvta.to.shared.u64 t, %1; cvt.u32.u64 %0, t; }" : "=r"(a) : "l"(p));
    return a;
}

#define LDSM4(r, addr) \
    asm volatile("ldmatrix.sync.aligned.m8n8.x4.shared.b16 {%0,%1,%2,%3}, [%4];" \
        : "=r"((r)[0]), "=r"((r)[1]), "=r"((r)[2]), "=r"((r)[3]) : "r"(addr))

#define MMA16816(c, a, b) \
    asm volatile("mma.sync.aligned.m16n8k16.row.col.f32.bf16.bf16.f32 " \
        "{%0,%1,%2,%3}, {%4,%5,%6,%7}, {%8,%9}, {%0,%1,%2,%3};" \
        : "+f"((c)[0]), "+f"((c)[1]), "+f"((c)[2]), "+f"((c)[3]) \
        : "r"((a)[0]), "r"((a)[1]), "r"((a)[2]), "r"((a)[3]), "r"((b)[0]), "r"((b)[1]))

#define CP16(dst, src) \
    asm volatile("cp.async.cg.shared.global [%0], [%1], 16;" :: "r"(dst), "l"(src))
#define CP_COMMIT() asm volatile("cp.async.commit_group;")

#define RCPF(r, x) asm("rcp.approx.f32 %0, %1;" : "=f"(r) : "f"(x))

__device__ __forceinline__ void hilo_pack(float4 x, uint2& ho, uint2& lo)
{
    __nv_bfloat16 h0 = __float2bfloat16(x.x), h1 = __float2bfloat16(x.y);
    __nv_bfloat16 h2 = __float2bfloat16(x.z), h3 = __float2bfloat16(x.w);
    __nv_bfloat16 l0 = __float2bfloat16(x.x - __bfloat162float(h0));
    __nv_bfloat16 l1 = __float2bfloat16(x.y - __bfloat162float(h1));
    __nv_bfloat16 l2 = __float2bfloat16(x.z - __bfloat162float(h2));
    __nv_bfloat16 l3 = __float2bfloat16(x.w - __bfloat162float(h3));
    __nv_bfloat162 hp0 = __halves2bfloat162(h0, h1), hp1 = __halves2bfloat162(h2, h3);
    __nv_bfloat162 lp0 = __halves2bfloat162(l0, l1), lp1 = __halves2bfloat162(l2, l3);
    ho.x = *reinterpret_cast<uint32_t*>(&hp0); ho.y = *reinterpret_cast<uint32_t*>(&hp1);
    lo.x = *reinterpret_cast<uint32_t*>(&lp0); lo.y = *reinterpret_cast<uint32_t*>(&lp1);
}

__device__ __forceinline__ void cvt4(const float* __restrict__ x,
                                     __nv_bfloat16* __restrict__ hi,
                                     __nv_bfloat16* __restrict__ lo, int i)
{
    float4 v = reinterpret_cast<const float4*>(x)[i];
    uint2 ho, loo;
    hilo_pack(v, ho, loo);
    reinterpret_cast<uint2*>(hi)[i] = ho;
    reinterpret_cast<uint2*>(lo)[i] = loo;
}

#define N4_Q  (BT*Hh/4)
#define N4_E  (Bb*Ss*Hh/4)
#define N4_WS (Hh*Hh/4)
#define N4_WO (Hh*2*Hh/4)
__global__ __launch_bounds__(256) void cvt_all(
    const float* q, const float* e, const float* ws, const float* wh, const float* wo)
{
    int i = blockIdx.x * blockDim.x + threadIdx.x;
    if (i < N4_Q)  { cvt4(q,  g_qh,  g_ql,  i); return; }  i -= N4_Q;
    if (i < N4_E)  { cvt4(e,  g_eh,  g_el,  i); return; }  i -= N4_E;
    if (i < N4_WS) { cvt4(ws, g_wcath, g_wcatl, i); return; }  i -= N4_WS;
    if (i < N4_WS) { cvt4(wh, g_whh, g_whl, i); return; }  i -= N4_WS;
    if (i < N4_WO) {
        int r = i >> 8, c4 = i & 255;
        float4 v = reinterpret_cast<const float4*>(wo)[i];
        uint2 ho, lo;
        hilo_pack(v, ho, lo);
        if (c4 < 128) {
            int di = r * 128 + c4;
            reinterpret_cast<uint2*>(g_wo1h)[di] = ho;
            reinterpret_cast<uint2*>(g_wo1l)[di] = lo;
        } else {
            int di = (512 + r) * 128 + (c4 - 128);
            reinterpret_cast<uint2*>(g_wcath)[di] = ho;
            reinterpret_cast<uint2*>(g_wcatl)[di] = lo;
        }
    }
}

// ---------------------------------------------------------------------------
// HMMA bf16x3 GEMM body. Template: STAGES = cp.async pipeline depth,
// MW = number of 32-row m-warps (4 -> 128x64 tile, 256 thr; 2 -> 64x64, 128 thr).
// modes: 1 exp(2x)->C ; 2 bf16 hi/lo -> Chi,Clo ; 3 tanh(x+QW)->C ;
//        5 split: n0<512 exp->C else linear->C2 (col-512)
// ---------------------------------------------------------------------------
template<int STAGES, int MW>
__device__ __noinline__ void gemm_body(
    const __nv_bfloat16* __restrict__ Ah, const __nv_bfloat16* __restrict__ Al,
    int astride,
    const __nv_bfloat16* __restrict__ Wh, const __nv_bfloat16* __restrict__ Wl,
    int wstride,
    float* __restrict__ C, float* __restrict__ C2,
    __nv_bfloat16* __restrict__ Chi, __nv_bfloat16* __restrict__ Clo,
    const float* __restrict__ QW,
    int NC, int Nout, int mode, size_t cofs, int m0, int n0)
{
    constexpr int AROWS  = MW * 32;
    constexpr int OFF_AL = AROWS * 80;
    constexpr int OFF_BH = 2 * AROWS * 80;
    constexpr int OFF_BL = OFF_BH + 5120;
    constexpr int STG    = OFF_BL + 5120;
    constexpr int T4     = MW * 16;          // threads/4

    extern __shared__ char smem[];
    const uint32_t sb = smem_u32(smem);

    const int tid = threadIdx.x;
    const int wid = tid >> 5, lane = tid & 31;
    const int wm = (wid & (MW - 1)) * 32;
    const int wn = (wid / MW) * 32;

    const int ar = tid >> 2;                 // [0, T4)
    const int ac = (tid & 3) * 8;
    const int g  = lane >> 3;
    const int rr = lane & 7;

    float acc[2][4][4];
    #pragma unroll
    for (int mi = 0; mi < 2; mi++)
        #pragma unroll
        for (int ni = 0; ni < 4; ni++)
            #pragma unroll
            for (int r = 0; r < 4; r++) acc[mi][ni][r] = 0.0f;

    auto load_stage = [&](int kc, int stg) {
        const int k0 = kc * 32;
        const uint32_t base = sb + stg * STG;
        #pragma unroll
        for (int r = 0; r < 2; r++) {
            int row = ar + r * T4;
            size_t gidx = (size_t)(m0 + row) * astride + k0 + ac;
            CP16(base + 0      + row * 80 + ac * 2, &Ah[gidx]);
            CP16(base + OFF_AL + row * 80 + ac * 2, &Al[gidx]);
        }
        #pragma unroll
        for (int row = 0; row < 64; row += T4) {
            int br = ar + row;
            if (br < 64) {
                size_t gw = (size_t)(n0 + br) * wstride + k0 + ac;
                CP16(base + OFF_BH + br * 80 + ac * 2, &Wh[gw]);
                CP16(base + OFF_BL + br * 80 + ac * 2, &Wl[gw]);
            }
        }
    };

    auto compute = [&](int stg) {
        const uint32_t base = sb + stg * STG;
        #pragma unroll
        for (int ks = 0; ks < 32; ks += 16) {
            uint32_t ah[2][4], al[2][4], bh[4][2], bl[4][2];
            const int colb = (ks + (g >> 1) * 8) * 2;
            #pragma unroll
            for (int mi = 0; mi < 2; mi++) {
                int row = wm + mi * 16 + (g & 1) * 8 + rr;
                LDSM4(ah[mi], base + 0      + row * 80 + colb);
                LDSM4(al[mi], base + OFF_AL + row * 80 + colb);
            }
            #pragma unroll
            for (int nb = 0; nb < 2; nb++) {
                int row = wn + nb * 16 + (g & 1) * 8 + rr;
                uint32_t t[4];
                LDSM4(t, base + OFF_BH + row * 80 + colb);
                bh[nb*2+0][0] = t[0]; bh[nb*2+0][1] = t[2];
                bh[nb*2+1][0] = t[1]; bh[nb*2+1][1] = t[3];
                LDSM4(t, base + OFF_BL + row * 80 + colb);
                bl[nb*2+0][0] = t[0]; bl[nb*2+0][1] = t[2];
                bl[nb*2+1][0] = t[1]; bl[nb*2+1][1] = t[3];
            }
            #pragma unroll
            for (int mi = 0; mi < 2; mi++)
                #pragma unroll
                for (int ni = 0; ni < 4; ni++) {
                    MMA16816(acc[mi][ni], ah[mi], bh[ni]);
                    MMA16816(acc[mi][ni], ah[mi], bl[ni]);
                    MMA16816(acc[mi][ni], al[mi], bh[ni]);
                }
        }
    };

    load_stage(0, 0);
    CP_COMMIT();
    if (STAGES == 3 && NC > 1) { load_stage(1, 1); CP_COMMIT(); }
    for (int kc = 0; kc < NC; kc++) {
        if (STAGES == 2) {
            if (kc + 1 < NC) {
                load_stage(kc + 1, (kc + 1) & 1);
                CP_COMMIT();
                asm volatile("cp.async.wait_group 1;");
            } else {
                asm volatile("cp.async.wait_group 0;");
            }
        } else {
            if (kc + 2 < NC) {
                load_stage(kc + 2, (kc + 2) % 3);
                CP_COMMIT();
                asm volatile("cp.async.wait_group 2;");
            } else if (kc + 1 < NC) {
                asm volatile("cp.async.wait_group 1;");
            } else {
                asm volatile("cp.async.wait_group 0;");
            }
        }
        __syncthreads();
        compute(kc % STAGES);
        __syncthreads();
    }

    #pragma unroll
    for (int mi = 0; mi < 2; mi++)
        #pragma unroll
        for (int ni = 0; ni < 4; ni++) {
            int row = m0 + wm + mi * 16 + (lane >> 2);
            int col = n0 + wn + ni * 8 + (lane & 3) * 2;
            float x0 = acc[mi][ni][0], x1 = acc[mi][ni][1];
            float x2 = acc[mi][ni][2], x3 = acc[mi][ni][3];
            if (mode == 1 || (mode == 5 && n0 < 512)) {
                float2 v0 = { __expf(2.0f * x0), __expf(2.0f * x1) };
                float2 v1 = { __expf(2.0f * x2), __expf(2.0f * x3) };
                *reinterpret_cast<float2*>(&C[cofs + (size_t)row * Nout + col]) = v0;
                *reinterpret_cast<float2*>(&C[cofs + (size_t)(row + 8) * Nout + col]) = v1;
            } else if (mode == 5) {
                int cq = col - 512;
                float2 v0 = { x0, x1 };
                float2 v1 = { x2, x3 };
                *reinterpret_cast<float2*>(&C2[(size_t)row * Nout + cq]) = v0;
                *reinterpret_cast<float2*>(&C2[(size_t)(row + 8) * Nout + cq]) = v1;
            } else if (mode == 2) {
                __nv_bfloat16 h0 = __float2bfloat16(x0), h1 = __float2bfloat16(x1);
                __nv_bfloat16 h2 = __float2bfloat16(x2), h3 = __float2bfloat16(x3);
                __nv_bfloat16 l0 = __float2bfloat16(x0 - __bfloat162float(h0));
                __nv_bfloat16 l1 = __float2bfloat16(x1 - __bfloat162float(h1));
                __nv_bfloat16 l2 = __float2bfloat16(x2 - __bfloat162float(h2));
                __nv_bfloat16 l3 = __float2bfloat16(x3 - __bfloat162float(h3));
                __nv_bfloat162 hp0 = __halves2bfloat162(h0, h1), hp1 = __halves2bfloat162(h2, h3);
                __nv_bfloat162 lp0 = __halves2bfloat162(l0, l1), lp1 = __halves2bfloat162(l2, l3);
                *reinterpret_cast<uint32_t*>(&Chi[cofs + (size_t)row * Nout + col]) = *reinterpret_cast<uint32_t*>(&hp0);
                *reinterpret_cast<uint32_t*>(&Chi[cofs + (size_t)(row + 8) * Nout + col]) = *reinterpret_cast<uint32_t*>(&hp1);
                *reinterpret_cast<uint32_t*>(&Clo[cofs + (size_t)row * Nout + col]) = *reinterpret_cast<uint32_t*>(&lp0);
                *reinterpret_cast<uint32_t*>(&Clo[cofs + (size_t)(row + 8) * Nout + col]) = *reinterpret_cast<uint32_t*>(&lp1);
            } else if (mode == 3) {
                float2 q0 = *reinterpret_cast<const float2*>(&QW[(size_t)row * Nout + col]);
                float2 q1 = *reinterpret_cast<const float2*>(&QW[(size_t)(row + 8) * Nout + col]);
                float2 v0 = { tanhf(x0 + q0.x), tanhf(x1 + q0.y) };
                float2 v1 = { tanhf(x2 + q1.x), tanhf(x3 + q1.y) };
                *reinterpret_cast<float2*>(&C[cofs + (size_t)row * Nout + col]) = v0;
                *reinterpret_cast<float2*>(&C[cofs + (size_t)(row + 8) * Nout + col]) = v1;
            }
        }
}

#define GEMM_SMEM_MW4 (2 * (2*128*80 + 2*5120))   // 61440
#define GEMM_SMEM_MW2 (2 * (2*64*80 + 2*5120))    // 40960

// ---------------------------------------------------------------------------
// Stage 1: fused G1 + K2 + K2b, 512 blocks, 3 CTAs/SM co-resident. (MW=4)
// ---------------------------------------------------------------------------
__global__ __launch_bounds__(256, 3) void stage1(const int* __restrict__ lens)
{
    const int bid = blockIdx.x;
    if (bid < 256) {
        int m0 = (bid >> 4) * 128, n0 = (bid & 15) * 64;
        gemm_body<2,4>(g_qh, g_ql, 512, g_wcath, g_wcatl, 512,
                       g_TA, g_QW, nullptr, nullptr, nullptr,
                       16, 512, 5, 0, m0, n0);
    } else if (bid < 384) {
        int local = bid - 256;
        int n0 = (local & 7) * 64, m0 = (local >> 3) * 128;
        if ((m0 & 255) >= lens[m0 >> 8]) return;
        gemm_body<2,4>(g_eh, g_el, 512, g_whh, g_whl, 512,
                       g_TB, nullptr, nullptr, nullptr, nullptr,
                       16, 512, 1, 0, m0, n0);
    } else {
        int local = bid - 384;
        int n0 = (local & 3) * 64, m0 = ((local >> 2) & 3) * 128;
        int bz = local >> 4;
        int L = (lens[bz] + 31) & ~31;
        if (n0 >= L) return;
        gemm_body<2,4>(g_wo1h, g_wo1l, 512,
                       g_eh + (size_t)bz * Ss * Hh, g_el + (size_t)bz * Ss * Hh, 512,
                       nullptr, nullptr, g_EWth, g_EWtl, nullptr,
                       16, 256, 2, (size_t)bz * Hh * Ss, m0, n0);
    }
}

// ---------------------------------------------------------------------------
// K5: out[b] = tanh(attnw[b] @ EWt[b]^T + QW[b]).
// MW=2 (64x64 tiles, 128 threads) -> grid (8,4,8) = 256 blocks, 4 CTAs/SM.
// ---------------------------------------------------------------------------
__global__ __launch_bounds__(128, 4) void k5_kernel(
    float* __restrict__ out, const int* __restrict__ lens)
{
    const int bz = blockIdx.z;
    int NC = (lens[bz] + 31) >> 5;
    if (NC > 8) NC = 8;
    const int m0 = blockIdx.y * 64, n0 = blockIdx.x * 64;
    gemm_body<2,2>(g_awh + (size_t)bz * Tt * Ss, g_awl + (size_t)bz * Tt * Ss, 256,
                   g_EWth + (size_t)bz * Hh * Ss, g_EWtl + (size_t)bz * Hh * Ss, 256,
                   out + (size_t)bz * Tt * Hh, nullptr, nullptr, nullptr,
                   g_QW + (size_t)bz * Tt * Hh,
                   NC, 512, 3, 0, m0, n0);
}

// ---------------------------------------------------------------------------
// K3: energies + softmax -> attn weights (bf16 hi/lo). (unchanged from R14)
// ---------------------------------------------------------------------------
#define BUF1F (272 * 36)
#define SMEM_ATTN ((4*BUF1F + 512 + 2*4096) * 4)

__global__ __launch_bounds__(1024) void attn_kernel(
    const float* __restrict__ v, const int* __restrict__ lens)
{
    extern __shared__ float sm[];
    float* vb  = sm + 4 * BUF1F;
    float* en0 = vb + 512;
    float* en1 = en0 + 4096;

    const uint32_t sb = smem_u32(sm);
    const int tid  = threadIdx.x;
    const int w    = tid >> 5;
    const int lane = tid & 31;
    const int hh    = w >> 4;
    const int wl    = w & 15;
    const int tg    = wl >> 3;
    const int stile = wl & 7;
    const int b  = blockIdx.y;
    const int t0 = blockIdx.x * 16;
    const int len = lens[b];
    const int lenc = (len + 31) & ~31;

    if (tid < 128)
        *reinterpret_cast<float4*>(&vb[tid * 4]) =
            *reinterpret_cast<const float4*>(&v[tid * 4]);

    auto load_pair = [&](int i, int par) {
        #pragma unroll
        for (int half = 0; half < 2; half++) {
            const int chunk = half * 8 + i;
            const uint32_t base = sb + (half * 2 + par) * (BUF1F * 4);
            #pragma unroll
            for (int k = 0; k < 2; k++) {
                int idx = tid + k * 1024;
                int row = idx >> 3, c4 = idx & 7;
                if (row < lenc)
                    CP16(base + (row * 36 + c4 * 4) * 4,
                         &g_TB[(size_t)(b * Ss + row) * Hh + chunk * 32 + c4 * 4]);
            }
            if (tid < 128) {
                int row = tid >> 3, c4 = tid & 7;
                CP16(base + ((256 + row) * 36 + c4 * 4) * 4,
                     &g_TA[(size_t)(b * Tt + t0 + row) * Hh + chunk * 32 + c4 * 4]);
            }
        }
    };

    float acc[8];
    #pragma unroll
    for (int j = 0; j < 8; j++) acc[j] = 0.0f;

    const bool active = (stile * 32) < len;

    load_pair(0, 0);
    CP_COMMIT();
    for (int i = 0; i < 8; i++) {
        if (i + 1 < 8) {
            load_pair(i + 1, (i + 1) & 1);
            CP_COMMIT();
            asm volatile("cp.async.wait_group 1;");
        } else {
            asm volatile("cp.async.wait_group 0;");
        }
        __syncthreads();

        if (active) {
            const float* bufp = sm + (hh * 2 + (i & 1)) * BUF1F;
            const float* erow = bufp + (stile * 32 + lane) * 36;
            const float* qg   = bufp + (256 + tg * 8) * 36;
            const float* vc   = vb + hh * 256 + i * 32;

            #pragma unroll 2
            for (int h4 = 0; h4 < 8; h4++) {
                float4 E = *reinterpret_cast<const float4*>(&erow[h4 * 4]);
                float4 V = *reinterpret_cast<const float4*>(&vc[h4 * 4]);
                #pragma unroll
                for (int j = 0; j < 8; j++) {
                    float4 A = *reinterpret_cast<const float4*>(&qg[j * 36 + h4 * 4]);
                    float d0 = fmaf(A.x, E.x, 1.0f);
                    float d1 = fmaf(A.y, E.y, 1.0f);
                    float d2 = fmaf(A.z, E.z, 1.0f);
                    float d3 = fmaf(A.w, E.w, 1.0f);
                    float n01 = fmaf(V.y, d0, V.x * d1);
                    float n23 = fmaf(V.w, d2, V.z * d3);
                    float p01 = d0 * d1, p23 = d2 * d3;
                    float r01, r23;
                    RCPF(r01, p01); RCPF(r23, p23);
                    acc[j] = fmaf(n01, r01, acc[j]);
                    acc[j] = fmaf(n23, r23, acc[j]);
                }
            }
        }
        __syncthreads();
    }

    if (active) {
        float* enp = hh ? en1 : en0;
        int s = stile * 32 + lane;
        #pragma unroll
        for (int j = 0; j < 8; j++)
            enp[(tg * 8 + j) * 256 + s] = acc[j];
    }
    __syncthreads();

    if (w < 16) {
        float e[8];
        float m = -INFINITY;
        #pragma unroll
        for (int j = 0; j < 8; j++) {
            int s = lane + 32 * j;
            int idx = w * 256 + s;
            e[j] = (s < len) ? (-2.0f * (en0[idx] + en1[idx])) : -INFINITY;
            m = fmaxf(m, e[j]);
        }
        #pragma unroll
        for (int o = 16; o; o >>= 1) m = fmaxf(m, __shfl_xor_sync(0xffffffffu, m, o));
        float sum = 0.0f;
        #pragma unroll
        for (int j = 0; j < 8; j++) { e[j] = __expf(e[j] - m); sum += e[j]; }
        #pragma unroll
        for (int o = 16; o; o >>= 1) sum += __shfl_xor_sync(0xffffffffu, sum, o);
        float rs; RCPF(rs, sum);
        #pragma unroll
        for (int j = 0; j < 8; j++) en0[w * 256 + lane + 32 * j] = e[j] * rs;
    }
    __syncthreads();

    {
        int row = tid >> 6, c4 = tid & 63;
        float4 x = *reinterpret_cast<const float4*>(&en0[row * 256 + c4 * 4]);
        uint2 ho, lo;
        hilo_pack(x, ho, lo);
        size_t gidx = (size_t)(b * Tt + t0 + row) * Ss + c4 * 4;
        *reinterpret_cast<uint2*>(&g_awh[gidx]) = ho;
        *reinterpret_cast<uint2*>(&g_awl[gidx]) = lo;
    }
}

// ---------------------------------------------------------------------------
extern "C" void kernel_launch(void* const* d_in, const int* in_sizes, int n_in,
                              void* d_out, int out_size)
{
    const float* query = (const float*)d_in[0];
    const float* enc   = (const float*)d_in[1];
    const int*   lens  = (const int*)d_in[2];
    const float* W_s   = (const float*)d_in[3];
    const float* W_h   = (const float*)d_in[4];
    const float* v     = (const float*)d_in[5];
    const float* W_out = (const float*)d_in[6];
    float* out = (float*)d_out;

    cudaFuncSetAttribute(attn_kernel,
                         cudaFuncAttributeMaxDynamicSharedMemorySize, SMEM_ATTN);
    cudaFuncSetAttribute(stage1,
                         cudaFuncAttributeMaxDynamicSharedMemorySize, GEMM_SMEM_MW4);
    cudaFuncSetAttribute(k5_kernel,
                         cudaFuncAttributeMaxDynamicSharedMemorySize, GEMM_SMEM_MW2);

    const int TOT4 = N4_Q + N4_E + 2 * N4_WS + N4_WO;
    cvt_all<<<TOT4 / 256, 256>>>(query, enc, W_s, W_h, W_out);

    // Stage 1: G1 + K2 + K2b fused (512 blocks, 3 CTAs/SM co-resident)
    stage1<<<512, 256, GEMM_SMEM_MW4>>>(lens);
    // K3: energies + softmax -> attn weights bf16 hi/lo (1024 threads)
    attn_kernel<<<dim3(Tt / 16, Bb), 1024, SMEM_ATTN>>>(v, lens);
    // K5: 64x64 tiles, 256 blocks, 4 CTAs/SM co-resident
    k5_kernel<<<dim3(8, 4, 8), 128, GEMM_SMEM_MW2>>>(out, lens);
}